// round 1
// baseline (speedup 1.0000x reference)
#include <cuda_runtime.h>
#include <math.h>

// Problem constants
#define BATCH 4
#define SEQ   2048
#define DIM   1024
#define NHEAD 16
#define HDIM  64
#define MLPD  4096
#define MTOK  (BATCH*SEQ)   // 8192 tokens

// -------- scratch (device globals; no allocation allowed) --------
__device__ __align__(16) float g_h  [(size_t)MTOK * DIM];      // 32 MB (rmsnorm out, reused)
__device__ __align__(16) float g_qkv[(size_t)MTOK * 3 * DIM];  // 96 MB
__device__ __align__(16) float g_o  [(size_t)MTOK * DIM];      // 32 MB (attention out)
__device__ __align__(16) float g_m1 [(size_t)MTOK * MLPD];     // 128 MB (mlp hidden)

// ---------------------------------------------------------------
// RMSNorm: one block per row of 1024, 256 threads, float4 per thread
// ---------------------------------------------------------------
__global__ __launch_bounds__(256) void rmsnorm_kernel(
    const float* __restrict__ x, const float* __restrict__ w, float* __restrict__ y)
{
    int row = blockIdx.x;
    const float4* xr = (const float4*)(x + (size_t)row * DIM);
    float4 v = xr[threadIdx.x];
    float ss = v.x*v.x + v.y*v.y + v.z*v.z + v.w*v.w;
    #pragma unroll
    for (int o = 16; o; o >>= 1) ss += __shfl_xor_sync(0xffffffffu, ss, o);
    __shared__ float red[8];
    if ((threadIdx.x & 31) == 0) red[threadIdx.x >> 5] = ss;
    __syncthreads();
    float tot = 0.f;
    #pragma unroll
    for (int i = 0; i < 8; ++i) tot += red[i];
    float inv = rsqrtf(tot * (1.0f / DIM) + 1e-6f);
    float4 wv = ((const float4*)w)[threadIdx.x];
    float4 out;
    out.x = v.x * inv * wv.x;
    out.y = v.y * inv * wv.y;
    out.z = v.z * inv * wv.z;
    out.w = v.w * inv * wv.w;
    ((float4*)(y + (size_t)row * DIM))[threadIdx.x] = out;
}

// ---------------------------------------------------------------
// Tiled fp32 GEMM: C[M,N] = A[M,K] @ B[K,N]  (+bias)(+silu)(+residual)
// 128x128 tile, BK=16, 256 threads, 8x8 per-thread microtile.
// M,N multiples of 128; K multiple of 16 (true for all calls here).
// ---------------------------------------------------------------
template<bool HAS_BIAS, bool DO_SILU, bool HAS_RES>
__global__ __launch_bounds__(256) void sgemm_kernel(
    const float* __restrict__ A, const float* __restrict__ Bm,
    float* __restrict__ C, const float* __restrict__ bias,
    const float* __restrict__ res, int N, int K)
{
    __shared__ float As[16][128];   // As[k][row] (transposed)
    __shared__ float Bs[16][128];   // Bs[k][col]

    int tid = threadIdx.x;
    int tx = tid & 15, ty = tid >> 4;
    int rowBase = blockIdx.y * 128;
    int colBase = blockIdx.x * 128;

    float acc[8][8];
    #pragma unroll
    for (int i = 0; i < 8; ++i)
        #pragma unroll
        for (int j = 0; j < 8; ++j) acc[i][j] = 0.f;

    for (int k0 = 0; k0 < K; k0 += 16) {
        // load A tile (128 rows x 16 k), transpose into As
        #pragma unroll
        for (int it = 0; it < 2; ++it) {
            int f = tid + it * 256;           // 512 float4
            int r = f >> 2;                   // 0..127
            int kq = (f & 3) * 4;             // 0,4,8,12
            float4 a = *(const float4*)(A + (size_t)(rowBase + r) * K + k0 + kq);
            As[kq + 0][r] = a.x; As[kq + 1][r] = a.y;
            As[kq + 2][r] = a.z; As[kq + 3][r] = a.w;
        }
        // load B tile (16 k x 128 cols)
        #pragma unroll
        for (int it = 0; it < 2; ++it) {
            int f = tid + it * 256;
            int kr = f >> 5;                  // 0..15
            int c  = (f & 31) * 4;            // 0..124
            *(float4*)&Bs[kr][c] =
                *(const float4*)(Bm + (size_t)(k0 + kr) * N + colBase + c);
        }
        __syncthreads();

        #pragma unroll
        for (int kk = 0; kk < 16; ++kk) {
            float a[8], b[8];
            *(float4*)(a)     = *(float4*)&As[kk][ty * 8];
            *(float4*)(a + 4) = *(float4*)&As[kk][ty * 8 + 4];
            *(float4*)(b)     = *(float4*)&Bs[kk][tx * 8];
            *(float4*)(b + 4) = *(float4*)&Bs[kk][tx * 8 + 4];
            #pragma unroll
            for (int i = 0; i < 8; ++i)
                #pragma unroll
                for (int j = 0; j < 8; ++j)
                    acc[i][j] = fmaf(a[i], b[j], acc[i][j]);
        }
        __syncthreads();
    }

    // epilogue
    #pragma unroll
    for (int i = 0; i < 8; ++i) {
        int r = rowBase + ty * 8 + i;
        float vv[8];
        #pragma unroll
        for (int j = 0; j < 8; ++j) {
            float v = acc[i][j];
            int c = colBase + tx * 8 + j;
            if (HAS_BIAS) v += bias[c];
            if (DO_SILU)  v = v / (1.f + __expf(-v));
            if (HAS_RES)  v += res[(size_t)r * N + c];
            vv[j] = v;
        }
        *(float4*)(C + (size_t)r * N + colBase + tx * 8)     = *(float4*)(vv);
        *(float4*)(C + (size_t)r * N + colBase + tx * 8 + 4) = *(float4*)(vv + 4);
    }
}

// ---------------------------------------------------------------
// Flash-attention (fp32). grid = (SEQ/64, NHEAD, BATCH), 256 threads.
// Per block: 64 query rows of one (b,h), online softmax over 32 key tiles.
// Thread (ty,tx) in 16x16 grid owns 4 score-rows x 4 cols microtiles.
// Dynamic smem: Qst | Kst | Vs | Pst, each 64*64 floats = 64 KB total.
// ---------------------------------------------------------------
__global__ __launch_bounds__(256) void attn_kernel(
    const float* __restrict__ qkv, float* __restrict__ o)
{
    extern __shared__ float sm[];
    float* Qst = sm;            // Qst[d][row]
    float* Kst = sm + 4096;     // Kst[d][col(key)]
    float* Vs  = sm + 8192;     // Vs[key][d]
    float* Pst = sm + 12288;    // Pst[key][row]

    int tid = threadIdx.x;
    int tx = tid & 15, ty = tid >> 4;
    int qb = blockIdx.x;        // query tile 0..31
    int h  = blockIdx.y;
    int b  = blockIdx.z;

    size_t tokbase = (size_t)b * SEQ;
    int qoff = h * HDIM;
    int koff = DIM + h * HDIM;
    int voff = 2 * DIM + h * HDIM;

    // load Q tile transposed: Qst[d][row]
    {
        int r  = tid >> 2;           // 0..63
        int d0 = (tid & 3) * 16;     // 16 floats per thread
        const float* src = qkv + (tokbase + qb * 64 + r) * (size_t)(3 * DIM) + qoff + d0;
        #pragma unroll
        for (int u = 0; u < 4; ++u) {
            float4 a = *(const float4*)(src + u * 4);
            int d = d0 + u * 4;
            Qst[(d + 0) * 64 + r] = a.x;
            Qst[(d + 1) * 64 + r] = a.y;
            Qst[(d + 2) * 64 + r] = a.z;
            Qst[(d + 3) * 64 + r] = a.w;
        }
    }

    float m_i[4], l_i[4], acc[4][4];
    #pragma unroll
    for (int i = 0; i < 4; ++i) {
        m_i[i] = -1e30f; l_i[i] = 0.f;
        #pragma unroll
        for (int j = 0; j < 4; ++j) acc[i][j] = 0.f;
    }

    for (int t = 0; t < SEQ / 64; ++t) {
        __syncthreads();  // protect Kst/Vs/Pst from previous iteration readers
        // load K (transposed) and V (direct)
        {
            int r  = tid >> 2;
            int d0 = (tid & 3) * 16;
            const float* ksrc = qkv + (tokbase + t * 64 + r) * (size_t)(3 * DIM) + koff + d0;
            const float* vsrc = qkv + (tokbase + t * 64 + r) * (size_t)(3 * DIM) + voff + d0;
            #pragma unroll
            for (int u = 0; u < 4; ++u) {
                float4 a = *(const float4*)(ksrc + u * 4);
                int d = d0 + u * 4;
                Kst[(d + 0) * 64 + r] = a.x;
                Kst[(d + 1) * 64 + r] = a.y;
                Kst[(d + 2) * 64 + r] = a.z;
                Kst[(d + 3) * 64 + r] = a.w;
                *(float4*)&Vs[r * 64 + d] = *(const float4*)(vsrc + u * 4);
            }
        }
        __syncthreads();

        // scores: s[i][j] = Q[row_i] . K[col_j]
        float s[4][4];
        #pragma unroll
        for (int i = 0; i < 4; ++i)
            #pragma unroll
            for (int j = 0; j < 4; ++j) s[i][j] = 0.f;
        #pragma unroll 8
        for (int kk = 0; kk < 64; ++kk) {
            float4 qa = *(float4*)&Qst[kk * 64 + ty * 4];
            float4 ka = *(float4*)&Kst[kk * 64 + tx * 4];
            float qv[4] = {qa.x, qa.y, qa.z, qa.w};
            float kv[4] = {ka.x, ka.y, ka.z, ka.w};
            #pragma unroll
            for (int i = 0; i < 4; ++i)
                #pragma unroll
                for (int j = 0; j < 4; ++j)
                    s[i][j] = fmaf(qv[i], kv[j], s[i][j]);
        }
        const float scale = 0.125f; // 1/sqrt(64)

        // online softmax update
        #pragma unroll
        for (int i = 0; i < 4; ++i) {
            float mx = -1e30f;
            #pragma unroll
            for (int j = 0; j < 4; ++j) { s[i][j] *= scale; mx = fmaxf(mx, s[i][j]); }
            #pragma unroll
            for (int off = 8; off; off >>= 1)
                mx = fmaxf(mx, __shfl_xor_sync(0xffffffffu, mx, off));
            float mnew = fmaxf(m_i[i], mx);
            float alpha = __expf(m_i[i] - mnew);
            float rs = 0.f;
            #pragma unroll
            for (int j = 0; j < 4; ++j) {
                float p = __expf(s[i][j] - mnew);
                s[i][j] = p;
                rs += p;
            }
            #pragma unroll
            for (int off = 8; off; off >>= 1)
                rs += __shfl_xor_sync(0xffffffffu, rs, off);
            l_i[i] = l_i[i] * alpha + rs;
            m_i[i] = mnew;
            #pragma unroll
            for (int j = 0; j < 4; ++j) acc[i][j] *= alpha;
        }

        // stage P transposed: Pst[key][row]
        #pragma unroll
        for (int i = 0; i < 4; ++i)
            #pragma unroll
            for (int j = 0; j < 4; ++j)
                Pst[(tx * 4 + j) * 64 + (ty * 4 + i)] = s[i][j];
        __syncthreads();

        // O accumulation: acc[i][j] += sum_key P[row_i][key] * V[key][d_j]
        #pragma unroll 8
        for (int kk = 0; kk < 64; ++kk) {
            float4 pa = *(float4*)&Pst[kk * 64 + ty * 4];
            float4 va = *(float4*)&Vs[kk * 64 + tx * 4];
            float pv[4] = {pa.x, pa.y, pa.z, pa.w};
            float vv[4] = {va.x, va.y, va.z, va.w};
            #pragma unroll
            for (int i = 0; i < 4; ++i)
                #pragma unroll
                for (int j = 0; j < 4; ++j)
                    acc[i][j] = fmaf(pv[i], vv[j], acc[i][j]);
        }
    }

    // write O (merged-head layout [token, h*64+d])
    #pragma unroll
    for (int i = 0; i < 4; ++i) {
        float inv = 1.f / l_i[i];
        float4 outv;
        outv.x = acc[i][0] * inv;
        outv.y = acc[i][1] * inv;
        outv.z = acc[i][2] * inv;
        outv.w = acc[i][3] * inv;
        size_t tok = tokbase + qb * 64 + ty * 4 + i;
        *(float4*)(o + tok * DIM + qoff + tx * 4) = outv;
    }
}

// ---------------------------------------------------------------
extern "C" void kernel_launch(void* const* d_in, const int* in_sizes, int n_in,
                              void* d_out, int out_size)
{
    const float* x     = (const float*)d_in[0];
    const float* n1w   = (const float*)d_in[1];
    const float* qkvw  = (const float*)d_in[2];
    const float* projw = (const float*)d_in[3];
    const float* projb = (const float*)d_in[4];
    const float* n2w   = (const float*)d_in[5];
    const float* fc1w  = (const float*)d_in[6];
    const float* fc1b  = (const float*)d_in[7];
    const float* fc2w  = (const float*)d_in[8];
    const float* fc2b  = (const float*)d_in[9];
    float* out = (float*)d_out;

    float *h, *qkv, *o, *m1;
    cudaGetSymbolAddress((void**)&h,   g_h);
    cudaGetSymbolAddress((void**)&qkv, g_qkv);
    cudaGetSymbolAddress((void**)&o,   g_o);
    cudaGetSymbolAddress((void**)&m1,  g_m1);

    cudaFuncSetAttribute(attn_kernel,
                         cudaFuncAttributeMaxDynamicSharedMemorySize, 65536);

    // 1) h = rmsnorm(x, norm1_w)
    rmsnorm_kernel<<<MTOK, 256>>>(x, n1w, h);
    // 2) qkv = h @ qkv_w
    sgemm_kernel<false, false, false><<<dim3(3 * DIM / 128, MTOK / 128), 256>>>(
        h, qkvw, qkv, nullptr, nullptr, 3 * DIM, DIM);
    // 3) attention -> o
    attn_kernel<<<dim3(SEQ / 64, NHEAD, BATCH), 256, 65536>>>(qkv, o);
    // 4) out = x + o @ proj_w + proj_b
    sgemm_kernel<true, false, true><<<dim3(DIM / 128, MTOK / 128), 256>>>(
        o, projw, out, projb, x, DIM, DIM);
    // 5) h = rmsnorm(out, norm2_w)
    rmsnorm_kernel<<<MTOK, 256>>>(out, n2w, h);
    // 6) m1 = silu(h @ fc1_w + fc1_b)
    sgemm_kernel<true, true, false><<<dim3(MLPD / 128, MTOK / 128), 256>>>(
        h, fc1w, m1, fc1b, nullptr, MLPD, DIM);
    // 7) out = out + m1 @ fc2_w + fc2_b
    sgemm_kernel<true, false, true><<<dim3(DIM / 128, MTOK / 128), 256>>>(
        m1, fc2w, out, fc2b, out, DIM, MLPD);
}

// round 2
// speedup vs baseline: 1.0003x; 1.0003x over previous
#include <cuda_runtime.h>
#include <math.h>

// Problem constants
#define BATCH 4
#define SEQ   2048
#define DIM   1024
#define NHEAD 16
#define HDIM  64
#define MLPD  4096
#define MTOK  (BATCH*SEQ)   // 8192 tokens

// -------- scratch (device globals; no allocation allowed) --------
__device__ __align__(16) float g_h  [(size_t)MTOK * DIM];      // 32 MB (rmsnorm out, reused)
__device__ __align__(16) float g_qkv[(size_t)MTOK * 3 * DIM];  // 96 MB
__device__ __align__(16) float g_o  [(size_t)MTOK * DIM];      // 32 MB (attention out)
__device__ __align__(16) float g_m1 [(size_t)MTOK * MLPD];     // 128 MB (mlp hidden)

// ---------------------------------------------------------------
// RMSNorm: one block per row of 1024, 256 threads, float4 per thread
// ---------------------------------------------------------------
__global__ __launch_bounds__(256) void rmsnorm_kernel(
    const float* __restrict__ x, const float* __restrict__ w, float* __restrict__ y)
{
    int row = blockIdx.x;
    const float4* xr = (const float4*)(x + (size_t)row * DIM);
    float4 v = xr[threadIdx.x];
    float ss = v.x*v.x + v.y*v.y + v.z*v.z + v.w*v.w;
    #pragma unroll
    for (int o = 16; o; o >>= 1) ss += __shfl_xor_sync(0xffffffffu, ss, o);
    __shared__ float red[8];
    if ((threadIdx.x & 31) == 0) red[threadIdx.x >> 5] = ss;
    __syncthreads();
    float tot = 0.f;
    #pragma unroll
    for (int i = 0; i < 8; ++i) tot += red[i];
    float inv = rsqrtf(tot * (1.0f / DIM) + 1e-6f);
    float4 wv = ((const float4*)w)[threadIdx.x];
    float4 out;
    out.x = v.x * inv * wv.x;
    out.y = v.y * inv * wv.y;
    out.z = v.z * inv * wv.z;
    out.w = v.w * inv * wv.w;
    ((float4*)(y + (size_t)row * DIM))[threadIdx.x] = out;
}

// ---------------------------------------------------------------
// Tiled fp32 GEMM: C[M,N] = A[M,K] @ B[K,N]  (+bias)(+silu)(+residual)
// 128x128 tile, BK=16, 256 threads, 8x8 per-thread microtile.
// M,N multiples of 128; K multiple of 16 (true for all calls here).
// ---------------------------------------------------------------
template<bool HAS_BIAS, bool DO_SILU, bool HAS_RES>
__global__ __launch_bounds__(256) void sgemm_kernel(
    const float* __restrict__ A, const float* __restrict__ Bm,
    float* __restrict__ C, const float* __restrict__ bias,
    const float* __restrict__ res, int N, int K)
{
    __shared__ float As[16][128];   // As[k][row] (transposed)
    __shared__ float Bs[16][128];   // Bs[k][col]

    int tid = threadIdx.x;
    int tx = tid & 15, ty = tid >> 4;
    int rowBase = blockIdx.y * 128;
    int colBase = blockIdx.x * 128;

    float acc[8][8];
    #pragma unroll
    for (int i = 0; i < 8; ++i)
        #pragma unroll
        for (int j = 0; j < 8; ++j) acc[i][j] = 0.f;

    for (int k0 = 0; k0 < K; k0 += 16) {
        // load A tile (128 rows x 16 k), transpose into As
        #pragma unroll
        for (int it = 0; it < 2; ++it) {
            int f = tid + it * 256;           // 512 float4
            int r = f >> 2;                   // 0..127
            int kq = (f & 3) * 4;             // 0,4,8,12
            float4 a = *(const float4*)(A + (size_t)(rowBase + r) * K + k0 + kq);
            As[kq + 0][r] = a.x; As[kq + 1][r] = a.y;
            As[kq + 2][r] = a.z; As[kq + 3][r] = a.w;
        }
        // load B tile (16 k x 128 cols)
        #pragma unroll
        for (int it = 0; it < 2; ++it) {
            int f = tid + it * 256;
            int kr = f >> 5;                  // 0..15
            int c  = (f & 31) * 4;            // 0..124
            *(float4*)&Bs[kr][c] =
                *(const float4*)(Bm + (size_t)(k0 + kr) * N + colBase + c);
        }
        __syncthreads();

        #pragma unroll
        for (int kk = 0; kk < 16; ++kk) {
            float a[8], b[8];
            *(float4*)(a)     = *(float4*)&As[kk][ty * 8];
            *(float4*)(a + 4) = *(float4*)&As[kk][ty * 8 + 4];
            *(float4*)(b)     = *(float4*)&Bs[kk][tx * 8];
            *(float4*)(b + 4) = *(float4*)&Bs[kk][tx * 8 + 4];
            #pragma unroll
            for (int i = 0; i < 8; ++i)
                #pragma unroll
                for (int j = 0; j < 8; ++j)
                    acc[i][j] = fmaf(a[i], b[j], acc[i][j]);
        }
        __syncthreads();
    }

    // epilogue
    #pragma unroll
    for (int i = 0; i < 8; ++i) {
        int r = rowBase + ty * 8 + i;
        float vv[8];
        #pragma unroll
        for (int j = 0; j < 8; ++j) {
            float v = acc[i][j];
            int c = colBase + tx * 8 + j;
            if (HAS_BIAS) v += bias[c];
            if (DO_SILU)  v = v / (1.f + __expf(-v));
            if (HAS_RES)  v += res[(size_t)r * N + c];
            vv[j] = v;
        }
        *(float4*)(C + (size_t)r * N + colBase + tx * 8)     = *(float4*)(vv);
        *(float4*)(C + (size_t)r * N + colBase + tx * 8 + 4) = *(float4*)(vv + 4);
    }
}

// ---------------------------------------------------------------
// Flash-attention (fp32). grid = (SEQ/64, NHEAD, BATCH), 256 threads.
// Per block: 64 query rows of one (b,h), online softmax over 32 key tiles.
// Thread (ty,tx) in 16x16 grid owns 4 score-rows x 4 cols microtiles.
// Dynamic smem: Qst | Kst | Vs | Pst, each 64*64 floats = 64 KB total.
// ---------------------------------------------------------------
__global__ __launch_bounds__(256) void attn_kernel(
    const float* __restrict__ qkv, float* __restrict__ o)
{
    extern __shared__ float sm[];
    float* Qst = sm;            // Qst[d][row]
    float* Kst = sm + 4096;     // Kst[d][col(key)]
    float* Vs  = sm + 8192;     // Vs[key][d]
    float* Pst = sm + 12288;    // Pst[key][row]

    int tid = threadIdx.x;
    int tx = tid & 15, ty = tid >> 4;
    int qb = blockIdx.x;        // query tile 0..31
    int h  = blockIdx.y;
    int b  = blockIdx.z;

    size_t tokbase = (size_t)b * SEQ;
    int qoff = h * HDIM;
    int koff = DIM + h * HDIM;
    int voff = 2 * DIM + h * HDIM;

    // load Q tile transposed: Qst[d][row]
    {
        int r  = tid >> 2;           // 0..63
        int d0 = (tid & 3) * 16;     // 16 floats per thread
        const float* src = qkv + (tokbase + qb * 64 + r) * (size_t)(3 * DIM) + qoff + d0;
        #pragma unroll
        for (int u = 0; u < 4; ++u) {
            float4 a = *(const float4*)(src + u * 4);
            int d = d0 + u * 4;
            Qst[(d + 0) * 64 + r] = a.x;
            Qst[(d + 1) * 64 + r] = a.y;
            Qst[(d + 2) * 64 + r] = a.z;
            Qst[(d + 3) * 64 + r] = a.w;
        }
    }

    float m_i[4], l_i[4], acc[4][4];
    #pragma unroll
    for (int i = 0; i < 4; ++i) {
        m_i[i] = -1e30f; l_i[i] = 0.f;
        #pragma unroll
        for (int j = 0; j < 4; ++j) acc[i][j] = 0.f;
    }

    for (int t = 0; t < SEQ / 64; ++t) {
        __syncthreads();  // protect Kst/Vs/Pst from previous iteration readers
        // load K (transposed) and V (direct)
        {
            int r  = tid >> 2;
            int d0 = (tid & 3) * 16;
            const float* ksrc = qkv + (tokbase + t * 64 + r) * (size_t)(3 * DIM) + koff + d0;
            const float* vsrc = qkv + (tokbase + t * 64 + r) * (size_t)(3 * DIM) + voff + d0;
            #pragma unroll
            for (int u = 0; u < 4; ++u) {
                float4 a = *(const float4*)(ksrc + u * 4);
                int d = d0 + u * 4;
                Kst[(d + 0) * 64 + r] = a.x;
                Kst[(d + 1) * 64 + r] = a.y;
                Kst[(d + 2) * 64 + r] = a.z;
                Kst[(d + 3) * 64 + r] = a.w;
                *(float4*)&Vs[r * 64 + d] = *(const float4*)(vsrc + u * 4);
            }
        }
        __syncthreads();

        // scores: s[i][j] = Q[row_i] . K[col_j]
        float s[4][4];
        #pragma unroll
        for (int i = 0; i < 4; ++i)
            #pragma unroll
            for (int j = 0; j < 4; ++j) s[i][j] = 0.f;
        #pragma unroll 8
        for (int kk = 0; kk < 64; ++kk) {
            float4 qa = *(float4*)&Qst[kk * 64 + ty * 4];
            float4 ka = *(float4*)&Kst[kk * 64 + tx * 4];
            float qv[4] = {qa.x, qa.y, qa.z, qa.w};
            float kv[4] = {ka.x, ka.y, ka.z, ka.w};
            #pragma unroll
            for (int i = 0; i < 4; ++i)
                #pragma unroll
                for (int j = 0; j < 4; ++j)
                    s[i][j] = fmaf(qv[i], kv[j], s[i][j]);
        }
        const float scale = 0.125f; // 1/sqrt(64)

        // online softmax update
        #pragma unroll
        for (int i = 0; i < 4; ++i) {
            float mx = -1e30f;
            #pragma unroll
            for (int j = 0; j < 4; ++j) { s[i][j] *= scale; mx = fmaxf(mx, s[i][j]); }
            #pragma unroll
            for (int off = 8; off; off >>= 1)
                mx = fmaxf(mx, __shfl_xor_sync(0xffffffffu, mx, off));
            float mnew = fmaxf(m_i[i], mx);
            float alpha = __expf(m_i[i] - mnew);
            float rs = 0.f;
            #pragma unroll
            for (int j = 0; j < 4; ++j) {
                float p = __expf(s[i][j] - mnew);
                s[i][j] = p;
                rs += p;
            }
            #pragma unroll
            for (int off = 8; off; off >>= 1)
                rs += __shfl_xor_sync(0xffffffffu, rs, off);
            l_i[i] = l_i[i] * alpha + rs;
            m_i[i] = mnew;
            #pragma unroll
            for (int j = 0; j < 4; ++j) acc[i][j] *= alpha;
        }

        // stage P transposed: Pst[key][row]
        #pragma unroll
        for (int i = 0; i < 4; ++i)
            #pragma unroll
            for (int j = 0; j < 4; ++j)
                Pst[(tx * 4 + j) * 64 + (ty * 4 + i)] = s[i][j];
        __syncthreads();

        // O accumulation: acc[i][j] += sum_key P[row_i][key] * V[key][d_j]
        #pragma unroll 8
        for (int kk = 0; kk < 64; ++kk) {
            float4 pa = *(float4*)&Pst[kk * 64 + ty * 4];
            float4 va = *(float4*)&Vs[kk * 64 + tx * 4];
            float pv[4] = {pa.x, pa.y, pa.z, pa.w};
            float vv[4] = {va.x, va.y, va.z, va.w};
            #pragma unroll
            for (int i = 0; i < 4; ++i)
                #pragma unroll
                for (int j = 0; j < 4; ++j)
                    acc[i][j] = fmaf(pv[i], vv[j], acc[i][j]);
        }
    }

    // write O (merged-head layout [token, h*64+d])
    #pragma unroll
    for (int i = 0; i < 4; ++i) {
        float inv = 1.f / l_i[i];
        float4 outv;
        outv.x = acc[i][0] * inv;
        outv.y = acc[i][1] * inv;
        outv.z = acc[i][2] * inv;
        outv.w = acc[i][3] * inv;
        size_t tok = tokbase + qb * 64 + ty * 4 + i;
        *(float4*)(o + tok * DIM + qoff + tx * 4) = outv;
    }
}

// ---------------------------------------------------------------
extern "C" void kernel_launch(void* const* d_in, const int* in_sizes, int n_in,
                              void* d_out, int out_size)
{
    const float* x     = (const float*)d_in[0];
    const float* n1w   = (const float*)d_in[1];
    const float* qkvw  = (const float*)d_in[2];
    const float* projw = (const float*)d_in[3];
    const float* projb = (const float*)d_in[4];
    const float* n2w   = (const float*)d_in[5];
    const float* fc1w  = (const float*)d_in[6];
    const float* fc1b  = (const float*)d_in[7];
    const float* fc2w  = (const float*)d_in[8];
    const float* fc2b  = (const float*)d_in[9];
    float* out = (float*)d_out;

    float *h, *qkv, *o, *m1;
    cudaGetSymbolAddress((void**)&h,   g_h);
    cudaGetSymbolAddress((void**)&qkv, g_qkv);
    cudaGetSymbolAddress((void**)&o,   g_o);
    cudaGetSymbolAddress((void**)&m1,  g_m1);

    cudaFuncSetAttribute(attn_kernel,
                         cudaFuncAttributeMaxDynamicSharedMemorySize, 65536);

    // 1) h = rmsnorm(x, norm1_w)
    rmsnorm_kernel<<<MTOK, 256>>>(x, n1w, h);
    // 2) qkv = h @ qkv_w
    sgemm_kernel<false, false, false><<<dim3(3 * DIM / 128, MTOK / 128), 256>>>(
        h, qkvw, qkv, nullptr, nullptr, 3 * DIM, DIM);
    // 3) attention -> o
    attn_kernel<<<dim3(SEQ / 64, NHEAD, BATCH), 256, 65536>>>(qkv, o);
    // 4) out = x + o @ proj_w + proj_b
    sgemm_kernel<true, false, true><<<dim3(DIM / 128, MTOK / 128), 256>>>(
        o, projw, out, projb, x, DIM, DIM);
    // 5) h = rmsnorm(out, norm2_w)
    rmsnorm_kernel<<<MTOK, 256>>>(out, n2w, h);
    // 6) m1 = silu(h @ fc1_w + fc1_b)
    sgemm_kernel<true, true, false><<<dim3(MLPD / 128, MTOK / 128), 256>>>(
        h, fc1w, m1, fc1b, nullptr, MLPD, DIM);
    // 7) out = out + m1 @ fc2_w + fc2_b
    sgemm_kernel<true, false, true><<<dim3(DIM / 128, MTOK / 128), 256>>>(
        m1, fc2w, out, fc2b, out, DIM, MLPD);
}

// round 3
// speedup vs baseline: 1.8147x; 1.8142x over previous
#include <cuda_runtime.h>
#include <math.h>
#include <stdint.h>

// Problem constants
#define BATCH 4
#define SEQ   2048
#define DIM   1024
#define NHEAD 16
#define HDIM  64
#define MLPD  4096
#define MTOK  (BATCH*SEQ)   // 8192 tokens

// -------- scratch (device globals; no allocation allowed) --------
__device__ __align__(16) float g_h  [(size_t)MTOK * DIM];      // 32 MB
__device__ __align__(16) float g_qkv[(size_t)MTOK * 3 * DIM];  // 96 MB
__device__ __align__(16) float g_o  [(size_t)MTOK * DIM];      // 32 MB
__device__ __align__(16) float g_m1 [(size_t)MTOK * MLPD];     // 128 MB

// ---------------------------------------------------------------
// RMSNorm: one block per row of 1024, 256 threads, float4 per thread
// ---------------------------------------------------------------
__global__ __launch_bounds__(256) void rmsnorm_kernel(
    const float* __restrict__ x, const float* __restrict__ w, float* __restrict__ y)
{
    int row = blockIdx.x;
    const float4* xr = (const float4*)(x + (size_t)row * DIM);
    float4 v = xr[threadIdx.x];
    float ss = v.x*v.x + v.y*v.y + v.z*v.z + v.w*v.w;
    #pragma unroll
    for (int o = 16; o; o >>= 1) ss += __shfl_xor_sync(0xffffffffu, ss, o);
    __shared__ float red[8];
    if ((threadIdx.x & 31) == 0) red[threadIdx.x >> 5] = ss;
    __syncthreads();
    float tot = 0.f;
    #pragma unroll
    for (int i = 0; i < 8; ++i) tot += red[i];
    float inv = rsqrtf(tot * (1.0f / DIM) + 1e-6f);
    float4 wv = ((const float4*)w)[threadIdx.x];
    float4 out;
    out.x = v.x * inv * wv.x;
    out.y = v.y * inv * wv.y;
    out.z = v.z * inv * wv.z;
    out.w = v.w * inv * wv.w;
    ((float4*)(y + (size_t)row * DIM))[threadIdx.x] = out;
}

// ---------------------------------------------------------------
// TF32 tensor-core GEMM: C[M,N] = A[M,K] @ B[K,N] (+bias)(+silu)(+res)
// 128x128 tile, BK=16, 256 threads (8 warps, 4x2), warp tile 32x64.
// mma.sync.m16n8k8 tf32, double-buffered smem, LDG->reg->STS pipeline.
// M,N multiples of 128; K multiple of 16.
// ---------------------------------------------------------------
#define AP 20    // As pitch (16 + 4 pad)  -> frag reads conflict-free
#define BP 132   // Bs pitch (128 + 4 pad) -> frag reads conflict-free

__device__ __forceinline__ uint32_t f2tf32(float f) {
    uint32_t r;
    asm("cvt.rna.tf32.f32 %0, %1;" : "=r"(r) : "f"(f));
    return r;
}

__device__ __forceinline__ void mma_tf32(
    float& d0, float& d1, float& d2, float& d3,
    uint32_t a0, uint32_t a1, uint32_t a2, uint32_t a3,
    uint32_t b0, uint32_t b1)
{
    asm volatile(
        "mma.sync.aligned.m16n8k8.row.col.f32.tf32.tf32.f32 "
        "{%0,%1,%2,%3}, {%4,%5,%6,%7}, {%8,%9}, {%0,%1,%2,%3};\n"
        : "+f"(d0), "+f"(d1), "+f"(d2), "+f"(d3)
        : "r"(a0), "r"(a1), "r"(a2), "r"(a3), "r"(b0), "r"(b1));
}

template<bool HAS_BIAS, bool DO_SILU, bool HAS_RES>
__global__ __launch_bounds__(256) void tf32gemm_kernel(
    const float* __restrict__ A, const float* __restrict__ Bm,
    float* __restrict__ C, const float* __restrict__ bias,
    const float* __restrict__ res, int N, int K)
{
    __shared__ uint32_t As[2][128 * AP];   // As[buf][row*AP + k]
    __shared__ uint32_t Bs[2][16 * BP];    // Bs[buf][k*BP + col]

    const int tid  = threadIdx.x;
    const int lane = tid & 31, warp = tid >> 5;
    const int wm = (warp & 3) * 32;        // warp row offset in tile
    const int wn = (warp >> 2) * 64;       // warp col offset in tile
    const int g  = lane >> 2, tig = lane & 3;
    const int rowBase = blockIdx.y * 128;
    const int colBase = blockIdx.x * 128;

    // global-load coordinates (128x16 A tile, 16x128 B tile; 512 float4 each)
    const int arow0 = tid >> 2;            // A: row = f>>2, kq = (f&3)*4
    const int akq0  = (tid & 3) << 2;
    const int brow0 = tid >> 5;            // B: row = f>>5, c = (f&31)*4
    const int bc0   = (tid & 31) << 2;

    float acc[2][8][4];
    #pragma unroll
    for (int mt = 0; mt < 2; ++mt)
        #pragma unroll
        for (int nt = 0; nt < 8; ++nt)
            #pragma unroll
            for (int q = 0; q < 4; ++q) acc[mt][nt][q] = 0.f;

    float4 aReg[2], bReg[2];

    auto ldg_tile = [&](int k0) {
        #pragma unroll
        for (int it = 0; it < 2; ++it) {
            int row = arow0 + it * 64;
            aReg[it] = *(const float4*)(A + (size_t)(rowBase + row) * K + k0 + akq0);
        }
        #pragma unroll
        for (int it = 0; it < 2; ++it) {
            int row = brow0 + it * 8;
            bReg[it] = *(const float4*)(Bm + (size_t)(k0 + row) * N + colBase + bc0);
        }
    };
    auto sts_tile = [&](int buf) {
        #pragma unroll
        for (int it = 0; it < 2; ++it) {
            int row = arow0 + it * 64;
            uint4 u;
            u.x = f2tf32(aReg[it].x); u.y = f2tf32(aReg[it].y);
            u.z = f2tf32(aReg[it].z); u.w = f2tf32(aReg[it].w);
            *(uint4*)&As[buf][row * AP + akq0] = u;
        }
        #pragma unroll
        for (int it = 0; it < 2; ++it) {
            int row = brow0 + it * 8;
            uint4 u;
            u.x = f2tf32(bReg[it].x); u.y = f2tf32(bReg[it].y);
            u.z = f2tf32(bReg[it].z); u.w = f2tf32(bReg[it].w);
            *(uint4*)&Bs[buf][row * BP + bc0] = u;
        }
    };
    auto compute = [&](int buf) {
        #pragma unroll
        for (int k8 = 0; k8 < 2; ++k8) {
            const int kb = k8 * 8;
            uint32_t af[2][4];
            #pragma unroll
            for (int mt = 0; mt < 2; ++mt) {
                int r = wm + mt * 16 + g;
                af[mt][0] = As[buf][ r      * AP + kb + tig];
                af[mt][1] = As[buf][(r + 8) * AP + kb + tig];
                af[mt][2] = As[buf][ r      * AP + kb + tig + 4];
                af[mt][3] = As[buf][(r + 8) * AP + kb + tig + 4];
            }
            uint32_t bf[8][2];
            #pragma unroll
            for (int nt = 0; nt < 8; ++nt) {
                int c = wn + nt * 8 + g;
                bf[nt][0] = Bs[buf][(kb + tig)     * BP + c];
                bf[nt][1] = Bs[buf][(kb + tig + 4) * BP + c];
            }
            #pragma unroll
            for (int mt = 0; mt < 2; ++mt)
                #pragma unroll
                for (int nt = 0; nt < 8; ++nt)
                    mma_tf32(acc[mt][nt][0], acc[mt][nt][1],
                             acc[mt][nt][2], acc[mt][nt][3],
                             af[mt][0], af[mt][1], af[mt][2], af[mt][3],
                             bf[nt][0], bf[nt][1]);
        }
    };

    // prologue
    ldg_tile(0);
    sts_tile(0);
    __syncthreads();

    int buf = 0;
    for (int k0 = 16; k0 < K; k0 += 16) {
        ldg_tile(k0);
        compute(buf);
        sts_tile(buf ^ 1);
        __syncthreads();
        buf ^= 1;
    }
    compute(buf);

    // epilogue: c0,c1 contiguous at (row g, col 2*tig); c2,c3 at row g+8
    #pragma unroll
    for (int mt = 0; mt < 2; ++mt) {
        #pragma unroll
        for (int nt = 0; nt < 8; ++nt) {
            int r0 = rowBase + wm + mt * 16 + g;
            int r1 = r0 + 8;
            int c  = colBase + wn + nt * 8 + 2 * tig;
            float v0 = acc[mt][nt][0], v1 = acc[mt][nt][1];
            float v2 = acc[mt][nt][2], v3 = acc[mt][nt][3];
            if (HAS_BIAS) {
                float b0 = bias[c], b1 = bias[c + 1];
                v0 += b0; v1 += b1; v2 += b0; v3 += b1;
            }
            if (DO_SILU) {
                v0 = v0 / (1.f + __expf(-v0));
                v1 = v1 / (1.f + __expf(-v1));
                v2 = v2 / (1.f + __expf(-v2));
                v3 = v3 / (1.f + __expf(-v3));
            }
            if (HAS_RES) {
                v0 += res[(size_t)r0 * N + c];
                v1 += res[(size_t)r0 * N + c + 1];
                v2 += res[(size_t)r1 * N + c];
                v3 += res[(size_t)r1 * N + c + 1];
            }
            float2 p0 = {v0, v1}, p1 = {v2, v3};
            *(float2*)(C + (size_t)r0 * N + c) = p0;
            *(float2*)(C + (size_t)r1 * N + c) = p1;
        }
    }
}

// ---------------------------------------------------------------
// Flash-attention (fp32). grid = (SEQ/64, NHEAD, BATCH), 256 threads.
// ---------------------------------------------------------------
__global__ __launch_bounds__(256) void attn_kernel(
    const float* __restrict__ qkv, float* __restrict__ o)
{
    extern __shared__ float sm[];
    float* Qst = sm;            // Qst[d][row]
    float* Kst = sm + 4096;     // Kst[d][col(key)]
    float* Vs  = sm + 8192;     // Vs[key][d]
    float* Pst = sm + 12288;    // Pst[key][row]

    int tid = threadIdx.x;
    int tx = tid & 15, ty = tid >> 4;
    int qb = blockIdx.x;
    int h  = blockIdx.y;
    int b  = blockIdx.z;

    size_t tokbase = (size_t)b * SEQ;
    int qoff = h * HDIM;
    int koff = DIM + h * HDIM;
    int voff = 2 * DIM + h * HDIM;

    {
        int r  = tid >> 2;
        int d0 = (tid & 3) * 16;
        const float* src = qkv + (tokbase + qb * 64 + r) * (size_t)(3 * DIM) + qoff + d0;
        #pragma unroll
        for (int u = 0; u < 4; ++u) {
            float4 a = *(const float4*)(src + u * 4);
            int d = d0 + u * 4;
            Qst[(d + 0) * 64 + r] = a.x;
            Qst[(d + 1) * 64 + r] = a.y;
            Qst[(d + 2) * 64 + r] = a.z;
            Qst[(d + 3) * 64 + r] = a.w;
        }
    }

    float m_i[4], l_i[4], acc[4][4];
    #pragma unroll
    for (int i = 0; i < 4; ++i) {
        m_i[i] = -1e30f; l_i[i] = 0.f;
        #pragma unroll
        for (int j = 0; j < 4; ++j) acc[i][j] = 0.f;
    }

    for (int t = 0; t < SEQ / 64; ++t) {
        __syncthreads();
        {
            int r  = tid >> 2;
            int d0 = (tid & 3) * 16;
            const float* ksrc = qkv + (tokbase + t * 64 + r) * (size_t)(3 * DIM) + koff + d0;
            const float* vsrc = qkv + (tokbase + t * 64 + r) * (size_t)(3 * DIM) + voff + d0;
            #pragma unroll
            for (int u = 0; u < 4; ++u) {
                float4 a = *(const float4*)(ksrc + u * 4);
                int d = d0 + u * 4;
                Kst[(d + 0) * 64 + r] = a.x;
                Kst[(d + 1) * 64 + r] = a.y;
                Kst[(d + 2) * 64 + r] = a.z;
                Kst[(d + 3) * 64 + r] = a.w;
                *(float4*)&Vs[r * 64 + d] = *(const float4*)(vsrc + u * 4);
            }
        }
        __syncthreads();

        float s[4][4];
        #pragma unroll
        for (int i = 0; i < 4; ++i)
            #pragma unroll
            for (int j = 0; j < 4; ++j) s[i][j] = 0.f;
        #pragma unroll 8
        for (int kk = 0; kk < 64; ++kk) {
            float4 qa = *(float4*)&Qst[kk * 64 + ty * 4];
            float4 ka = *(float4*)&Kst[kk * 64 + tx * 4];
            float qv[4] = {qa.x, qa.y, qa.z, qa.w};
            float kv[4] = {ka.x, ka.y, ka.z, ka.w};
            #pragma unroll
            for (int i = 0; i < 4; ++i)
                #pragma unroll
                for (int j = 0; j < 4; ++j)
                    s[i][j] = fmaf(qv[i], kv[j], s[i][j]);
        }
        const float scale = 0.125f;

        #pragma unroll
        for (int i = 0; i < 4; ++i) {
            float mx = -1e30f;
            #pragma unroll
            for (int j = 0; j < 4; ++j) { s[i][j] *= scale; mx = fmaxf(mx, s[i][j]); }
            #pragma unroll
            for (int off = 8; off; off >>= 1)
                mx = fmaxf(mx, __shfl_xor_sync(0xffffffffu, mx, off));
            float mnew = fmaxf(m_i[i], mx);
            float alpha = __expf(m_i[i] - mnew);
            float rs = 0.f;
            #pragma unroll
            for (int j = 0; j < 4; ++j) {
                float p = __expf(s[i][j] - mnew);
                s[i][j] = p;
                rs += p;
            }
            #pragma unroll
            for (int off = 8; off; off >>= 1)
                rs += __shfl_xor_sync(0xffffffffu, rs, off);
            l_i[i] = l_i[i] * alpha + rs;
            m_i[i] = mnew;
            #pragma unroll
            for (int j = 0; j < 4; ++j) acc[i][j] *= alpha;
        }

        #pragma unroll
        for (int i = 0; i < 4; ++i)
            #pragma unroll
            for (int j = 0; j < 4; ++j)
                Pst[(tx * 4 + j) * 64 + (ty * 4 + i)] = s[i][j];
        __syncthreads();

        #pragma unroll 8
        for (int kk = 0; kk < 64; ++kk) {
            float4 pa = *(float4*)&Pst[kk * 64 + ty * 4];
            float4 va = *(float4*)&Vs[kk * 64 + tx * 4];
            float pv[4] = {pa.x, pa.y, pa.z, pa.w};
            float vv[4] = {va.x, va.y, va.z, va.w};
            #pragma unroll
            for (int i = 0; i < 4; ++i)
                #pragma unroll
                for (int j = 0; j < 4; ++j)
                    acc[i][j] = fmaf(pv[i], vv[j], acc[i][j]);
        }
    }

    #pragma unroll
    for (int i = 0; i < 4; ++i) {
        float inv = 1.f / l_i[i];
        float4 outv;
        outv.x = acc[i][0] * inv;
        outv.y = acc[i][1] * inv;
        outv.z = acc[i][2] * inv;
        outv.w = acc[i][3] * inv;
        size_t tok = tokbase + qb * 64 + ty * 4 + i;
        *(float4*)(o + tok * DIM + qoff + tx * 4) = outv;
    }
}

// ---------------------------------------------------------------
extern "C" void kernel_launch(void* const* d_in, const int* in_sizes, int n_in,
                              void* d_out, int out_size)
{
    const float* x     = (const float*)d_in[0];
    const float* n1w   = (const float*)d_in[1];
    const float* qkvw  = (const float*)d_in[2];
    const float* projw = (const float*)d_in[3];
    const float* projb = (const float*)d_in[4];
    const float* n2w   = (const float*)d_in[5];
    const float* fc1w  = (const float*)d_in[6];
    const float* fc1b  = (const float*)d_in[7];
    const float* fc2w  = (const float*)d_in[8];
    const float* fc2b  = (const float*)d_in[9];
    float* out = (float*)d_out;

    float *h, *qkv, *o, *m1;
    cudaGetSymbolAddress((void**)&h,   g_h);
    cudaGetSymbolAddress((void**)&qkv, g_qkv);
    cudaGetSymbolAddress((void**)&o,   g_o);
    cudaGetSymbolAddress((void**)&m1,  g_m1);

    cudaFuncSetAttribute(attn_kernel,
                         cudaFuncAttributeMaxDynamicSharedMemorySize, 65536);

    // 1) h = rmsnorm(x, norm1_w)
    rmsnorm_kernel<<<MTOK, 256>>>(x, n1w, h);
    // 2) qkv = h @ qkv_w
    tf32gemm_kernel<false, false, false><<<dim3(3 * DIM / 128, MTOK / 128), 256>>>(
        h, qkvw, qkv, nullptr, nullptr, 3 * DIM, DIM);
    // 3) attention -> o
    attn_kernel<<<dim3(SEQ / 64, NHEAD, BATCH), 256, 65536>>>(qkv, o);
    // 4) out = x + o @ proj_w + proj_b
    tf32gemm_kernel<true, false, true><<<dim3(DIM / 128, MTOK / 128), 256>>>(
        o, projw, out, projb, x, DIM, DIM);
    // 5) h = rmsnorm(out, norm2_w)
    rmsnorm_kernel<<<MTOK, 256>>>(out, n2w, h);
    // 6) m1 = silu(h @ fc1_w + fc1_b)
    tf32gemm_kernel<true, true, false><<<dim3(MLPD / 128, MTOK / 128), 256>>>(
        h, fc1w, m1, fc1b, nullptr, MLPD, DIM);
    // 7) out = out + m1 @ fc2_w + fc2_b
    tf32gemm_kernel<true, false, true><<<dim3(DIM / 128, MTOK / 128), 256>>>(
        m1, fc2w, out, fc2b, out, DIM, MLPD);
}

// round 4
// speedup vs baseline: 2.6839x; 1.4790x over previous
#include <cuda_runtime.h>
#include <math.h>
#include <stdint.h>

// Problem constants
#define BATCH 4
#define SEQ   2048
#define DIM   1024
#define NHEAD 16
#define HDIM  64
#define MLPD  4096
#define MTOK  (BATCH*SEQ)   // 8192 tokens

// -------- scratch (device globals; no allocation allowed) --------
__device__ __align__(16) float g_h  [(size_t)MTOK * DIM];      // 32 MB
__device__ __align__(16) float g_qkv[(size_t)MTOK * 3 * DIM];  // 96 MB
__device__ __align__(16) float g_o  [(size_t)MTOK * DIM];      // 32 MB
__device__ __align__(16) float g_m1 [(size_t)MTOK * MLPD];     // 128 MB

// ---------------------------------------------------------------
// common helpers
// ---------------------------------------------------------------
__device__ __forceinline__ void mma_tf32(
    float& d0, float& d1, float& d2, float& d3,
    uint32_t a0, uint32_t a1, uint32_t a2, uint32_t a3,
    uint32_t b0, uint32_t b1)
{
    asm volatile(
        "mma.sync.aligned.m16n8k8.row.col.f32.tf32.tf32.f32 "
        "{%0,%1,%2,%3}, {%4,%5,%6,%7}, {%8,%9}, {%0,%1,%2,%3};\n"
        : "+f"(d0), "+f"(d1), "+f"(d2), "+f"(d3)
        : "r"(a0), "r"(a1), "r"(a2), "r"(a3), "r"(b0), "r"(b1));
}

__device__ __forceinline__ void cp16(uint32_t smem_dst, const void* gsrc) {
    asm volatile("cp.async.cg.shared.global [%0], [%1], 16;\n"
                 :: "r"(smem_dst), "l"(gsrc));
}
__device__ __forceinline__ void cp_commit() {
    asm volatile("cp.async.commit_group;\n");
}
__device__ __forceinline__ void cp_wait0() {
    asm volatile("cp.async.wait_group 0;\n");
}

// ---------------------------------------------------------------
// RMSNorm: one block per row of 1024, 256 threads, float4 per thread
// ---------------------------------------------------------------
__global__ __launch_bounds__(256) void rmsnorm_kernel(
    const float* __restrict__ x, const float* __restrict__ w, float* __restrict__ y)
{
    int row = blockIdx.x;
    const float4* xr = (const float4*)(x + (size_t)row * DIM);
    float4 v = xr[threadIdx.x];
    float ss = v.x*v.x + v.y*v.y + v.z*v.z + v.w*v.w;
    #pragma unroll
    for (int o = 16; o; o >>= 1) ss += __shfl_xor_sync(0xffffffffu, ss, o);
    __shared__ float red[8];
    if ((threadIdx.x & 31) == 0) red[threadIdx.x >> 5] = ss;
    __syncthreads();
    float tot = 0.f;
    #pragma unroll
    for (int i = 0; i < 8; ++i) tot += red[i];
    float inv = rsqrtf(tot * (1.0f / DIM) + 1e-6f);
    float4 wv = ((const float4*)w)[threadIdx.x];
    float4 out;
    out.x = v.x * inv * wv.x;
    out.y = v.y * inv * wv.y;
    out.z = v.z * inv * wv.z;
    out.w = v.w * inv * wv.w;
    ((float4*)(y + (size_t)row * DIM))[threadIdx.x] = out;
}

// ---------------------------------------------------------------
// TF32 GEMM v2: C[M,N] = A@B (+bias)(+silu)(+res)
// Block tile 256x128, BK=16, 256 threads (8 warps 4x2), warp tile 64x64.
// cp.async double-buffered; raw fp32 bits fed to tf32 mma (hw truncation).
// ---------------------------------------------------------------
#define AP 20    // As pitch words (16+4): A-frag reads conflict-free
#define BP 136   // Bs pitch words (128+8): B-frag reads conflict-free
#define ASZ (256 * AP)
#define BSZ (16 * BP)
#define GEMM_SMEM (2 * (ASZ + BSZ) * 4)

template<bool HAS_BIAS, bool DO_SILU, bool HAS_RES>
__global__ __launch_bounds__(256, 1) void tf32gemm_kernel(
    const float* __restrict__ A, const float* __restrict__ Bm,
    float* __restrict__ C, const float* __restrict__ bias,
    const float* __restrict__ res, int N, int K)
{
    extern __shared__ uint32_t sm[];
    uint32_t* As = sm;                    // [2][ASZ]
    uint32_t* Bs = sm + 2 * ASZ;          // [2][BSZ]

    const int tid  = threadIdx.x;
    const int lane = tid & 31, warp = tid >> 5;
    const int wm = (warp & 3) * 64;       // warp row offset
    const int wn = (warp >> 2) * 64;      // warp col offset
    const int g  = lane >> 2, tig = lane & 3;
    const int rowBase = blockIdx.y * 256;
    const int colBase = blockIdx.x * 128;

    const uint32_t sbase = (uint32_t)__cvta_generic_to_shared(sm);

    // async copy coordinates: A 256x16 -> 1024 16B chunks; B 16x128 -> 512
    const int ar0 = tid >> 2;             // +64 per it (4 its)
    const int akq = (tid & 3) << 2;
    const int br0 = tid >> 5;             // +8 per it (2 its)
    const int bc  = (tid & 31) << 2;

    auto ldg_async = [&](int k0, int buf) {
        uint32_t abase = sbase + (buf * ASZ) * 4;
        #pragma unroll
        for (int it = 0; it < 4; ++it) {
            int row = ar0 + it * 64;
            cp16(abase + (row * AP + akq) * 4,
                 A + (size_t)(rowBase + row) * K + k0 + akq);
        }
        uint32_t bbase = sbase + (2 * ASZ + buf * BSZ) * 4;
        #pragma unroll
        for (int it = 0; it < 2; ++it) {
            int row = br0 + it * 8;
            cp16(bbase + (row * BP + bc) * 4,
                 Bm + (size_t)(k0 + row) * N + colBase + bc);
        }
        cp_commit();
    };

    float acc[4][8][4];
    #pragma unroll
    for (int mt = 0; mt < 4; ++mt)
        #pragma unroll
        for (int nt = 0; nt < 8; ++nt)
            #pragma unroll
            for (int q = 0; q < 4; ++q) acc[mt][nt][q] = 0.f;

    auto compute = [&](int buf) {
        const uint32_t* Ab = As + buf * ASZ;
        const uint32_t* Bb = Bs + buf * BSZ;
        #pragma unroll
        for (int k8 = 0; k8 < 2; ++k8) {
            const int kb = k8 * 8;
            uint32_t af[4][4];
            #pragma unroll
            for (int mt = 0; mt < 4; ++mt) {
                int r = wm + mt * 16 + g;
                af[mt][0] = Ab[ r      * AP + kb + tig];
                af[mt][1] = Ab[(r + 8) * AP + kb + tig];
                af[mt][2] = Ab[ r      * AP + kb + tig + 4];
                af[mt][3] = Ab[(r + 8) * AP + kb + tig + 4];
            }
            uint32_t bf[8][2];
            #pragma unroll
            for (int nt = 0; nt < 8; ++nt) {
                int c = wn + nt * 8 + g;
                bf[nt][0] = Bb[(kb + tig)     * BP + c];
                bf[nt][1] = Bb[(kb + tig + 4) * BP + c];
            }
            #pragma unroll
            for (int mt = 0; mt < 4; ++mt)
                #pragma unroll
                for (int nt = 0; nt < 8; ++nt)
                    mma_tf32(acc[mt][nt][0], acc[mt][nt][1],
                             acc[mt][nt][2], acc[mt][nt][3],
                             af[mt][0], af[mt][1], af[mt][2], af[mt][3],
                             bf[nt][0], bf[nt][1]);
        }
    };

    // pipeline
    ldg_async(0, 0);
    cp_wait0();
    __syncthreads();

    int buf = 0;
    for (int k0 = 16; k0 < K; k0 += 16) {
        ldg_async(k0, buf ^ 1);
        compute(buf);
        cp_wait0();
        __syncthreads();
        buf ^= 1;
    }
    compute(buf);

    // epilogue
    #pragma unroll
    for (int mt = 0; mt < 4; ++mt) {
        #pragma unroll
        for (int nt = 0; nt < 8; ++nt) {
            int r0 = rowBase + wm + mt * 16 + g;
            int r1 = r0 + 8;
            int c  = colBase + wn + nt * 8 + 2 * tig;
            float v0 = acc[mt][nt][0], v1 = acc[mt][nt][1];
            float v2 = acc[mt][nt][2], v3 = acc[mt][nt][3];
            if (HAS_BIAS) {
                float b0 = bias[c], b1 = bias[c + 1];
                v0 += b0; v1 += b1; v2 += b0; v3 += b1;
            }
            if (DO_SILU) {
                v0 = v0 / (1.f + __expf(-v0));
                v1 = v1 / (1.f + __expf(-v1));
                v2 = v2 / (1.f + __expf(-v2));
                v3 = v3 / (1.f + __expf(-v3));
            }
            if (HAS_RES) {
                v0 += res[(size_t)r0 * N + c];
                v1 += res[(size_t)r0 * N + c + 1];
                v2 += res[(size_t)r1 * N + c];
                v3 += res[(size_t)r1 * N + c + 1];
            }
            float2 p0 = {v0, v1}, p1 = {v2, v3};
            *(float2*)(C + (size_t)r0 * N + c) = p0;
            *(float2*)(C + (size_t)r1 * N + c) = p1;
        }
    }
}

// ---------------------------------------------------------------
// TF32 flash attention. grid=(SEQ/64, NHEAD, BATCH), 128 threads (4 warps).
// Each warp owns 16 query rows x all 64 key cols / 64 output dims.
// Smem (dynamic): Q[64][QP], Kst[64][KP] (d-major), Vs[64][KP], Pst[64][QP].
// Pitches: QP=76 (A-frag reads: banks g*12+tig, distinct)
//          KP=72 (B-frag reads: banks tig*8+g, distinct)
// ---------------------------------------------------------------
#define QP 76
#define KP 72
#define ATTN_SMEM ((64*QP + 64*KP + 64*KP + 64*QP) * 4)

__global__ __launch_bounds__(128) void attn_kernel(
    const float* __restrict__ qkv, float* __restrict__ o)
{
    extern __shared__ float smf[];
    float* Qs  = smf;                 // [64][QP] row-major (row=query, col=d)
    float* Kst = Qs  + 64 * QP;       // [64][KP] (row=d, col=key)
    float* Vs  = Kst + 64 * KP;       // [64][KP] (row=key, col=d)
    float* Pst = Vs  + 64 * KP;       // [64][QP] (row=query, col=key)

    const int tid  = threadIdx.x;
    const int lane = tid & 31, warp = tid >> 5;
    const int g = lane >> 2, tig = lane & 3;
    const int wrow = warp * 16;

    const int qb = blockIdx.x, h = blockIdx.y, b = blockIdx.z;
    const size_t tokbase = (size_t)b * SEQ;
    const int qoff = h * HDIM;
    const int koff = DIM + h * HDIM;
    const int voff = 2 * DIM + h * HDIM;

    // load Q tile: 64 rows x 64 d; 128 threads, each 8 float4
    {
        int r  = tid >> 1;
        int d0 = (tid & 1) * 32;
        const float* src = qkv + (tokbase + qb * 64 + r) * (size_t)(3 * DIM) + qoff + d0;
        #pragma unroll
        for (int u = 0; u < 8; ++u)
            *(float4*)&Qs[r * QP + d0 + u * 4] = *(const float4*)(src + u * 4);
    }

    float m_i[2], l_i[2], oa[8][4];
    m_i[0] = m_i[1] = -1e30f;
    l_i[0] = l_i[1] = 0.f;
    #pragma unroll
    for (int nt = 0; nt < 8; ++nt)
        #pragma unroll
        for (int q = 0; q < 4; ++q) oa[nt][q] = 0.f;

    for (int t = 0; t < SEQ / 64; ++t) {
        __syncthreads();   // previous-iter readers of Kst/Vs done; Q load done (t=0)
        // load K (transposed to d-major) and V (row-major)
        {
            int r  = tid >> 1;           // key index 0..63
            int d0 = (tid & 1) * 32;
            const float* ksrc = qkv + (tokbase + t * 64 + r) * (size_t)(3 * DIM) + koff + d0;
            const float* vsrc = qkv + (tokbase + t * 64 + r) * (size_t)(3 * DIM) + voff + d0;
            #pragma unroll
            for (int u = 0; u < 8; ++u) {
                float4 a = *(const float4*)(ksrc + u * 4);
                int d = d0 + u * 4;
                Kst[(d + 0) * KP + r] = a.x;
                Kst[(d + 1) * KP + r] = a.y;
                Kst[(d + 2) * KP + r] = a.z;
                Kst[(d + 3) * KP + r] = a.w;
                *(float4*)&Vs[r * KP + d] = *(const float4*)(vsrc + u * 4);
            }
        }
        __syncthreads();

        // S = Q @ K^T : per warp 16x64, k=64
        float s[8][4];
        #pragma unroll
        for (int nt = 0; nt < 8; ++nt)
            #pragma unroll
            for (int q = 0; q < 4; ++q) s[nt][q] = 0.f;
        #pragma unroll
        for (int kb = 0; kb < 8; ++kb) {
            uint32_t a0 = __float_as_uint(Qs[(wrow + g)     * QP + kb * 8 + tig]);
            uint32_t a1 = __float_as_uint(Qs[(wrow + g + 8) * QP + kb * 8 + tig]);
            uint32_t a2 = __float_as_uint(Qs[(wrow + g)     * QP + kb * 8 + tig + 4]);
            uint32_t a3 = __float_as_uint(Qs[(wrow + g + 8) * QP + kb * 8 + tig + 4]);
            #pragma unroll
            for (int nt = 0; nt < 8; ++nt) {
                uint32_t b0 = __float_as_uint(Kst[(kb * 8 + tig)     * KP + nt * 8 + g]);
                uint32_t b1 = __float_as_uint(Kst[(kb * 8 + tig + 4) * KP + nt * 8 + g]);
                mma_tf32(s[nt][0], s[nt][1], s[nt][2], s[nt][3],
                         a0, a1, a2, a3, b0, b1);
            }
        }

        // online softmax (rows g and g+8 of this warp's band)
        const float scale = 0.125f;
        float mx0 = -1e30f, mx1 = -1e30f;
        #pragma unroll
        for (int nt = 0; nt < 8; ++nt) {
            s[nt][0] *= scale; s[nt][1] *= scale;
            s[nt][2] *= scale; s[nt][3] *= scale;
            mx0 = fmaxf(mx0, fmaxf(s[nt][0], s[nt][1]));
            mx1 = fmaxf(mx1, fmaxf(s[nt][2], s[nt][3]));
        }
        #pragma unroll
        for (int off = 1; off <= 2; off <<= 1) {
            mx0 = fmaxf(mx0, __shfl_xor_sync(0xffffffffu, mx0, off));
            mx1 = fmaxf(mx1, __shfl_xor_sync(0xffffffffu, mx1, off));
        }
        float mn0 = fmaxf(m_i[0], mx0), mn1 = fmaxf(m_i[1], mx1);
        float al0 = __expf(m_i[0] - mn0), al1 = __expf(m_i[1] - mn1);
        float rs0 = 0.f, rs1 = 0.f;
        #pragma unroll
        for (int nt = 0; nt < 8; ++nt) {
            s[nt][0] = __expf(s[nt][0] - mn0);
            s[nt][1] = __expf(s[nt][1] - mn0);
            s[nt][2] = __expf(s[nt][2] - mn1);
            s[nt][3] = __expf(s[nt][3] - mn1);
            rs0 += s[nt][0] + s[nt][1];
            rs1 += s[nt][2] + s[nt][3];
        }
        #pragma unroll
        for (int off = 1; off <= 2; off <<= 1) {
            rs0 += __shfl_xor_sync(0xffffffffu, rs0, off);
            rs1 += __shfl_xor_sync(0xffffffffu, rs1, off);
        }
        l_i[0] = l_i[0] * al0 + rs0;
        l_i[1] = l_i[1] * al1 + rs1;
        m_i[0] = mn0; m_i[1] = mn1;
        #pragma unroll
        for (int nt = 0; nt < 8; ++nt) {
            oa[nt][0] *= al0; oa[nt][1] *= al0;
            oa[nt][2] *= al1; oa[nt][3] *= al1;
        }

        // stage P (warp-private rows): Pst[row][key]
        #pragma unroll
        for (int nt = 0; nt < 8; ++nt) {
            int c = nt * 8 + 2 * tig;
            Pst[(wrow + g)     * QP + c]     = s[nt][0];
            Pst[(wrow + g)     * QP + c + 1] = s[nt][1];
            Pst[(wrow + g + 8) * QP + c]     = s[nt][2];
            Pst[(wrow + g + 8) * QP + c + 1] = s[nt][3];
        }
        __syncwarp();

        // O += P @ V : k=keys 64, n=d 64
        #pragma unroll
        for (int kb = 0; kb < 8; ++kb) {
            uint32_t a0 = __float_as_uint(Pst[(wrow + g)     * QP + kb * 8 + tig]);
            uint32_t a1 = __float_as_uint(Pst[(wrow + g + 8) * QP + kb * 8 + tig]);
            uint32_t a2 = __float_as_uint(Pst[(wrow + g)     * QP + kb * 8 + tig + 4]);
            uint32_t a3 = __float_as_uint(Pst[(wrow + g + 8) * QP + kb * 8 + tig + 4]);
            #pragma unroll
            for (int nt = 0; nt < 8; ++nt) {
                uint32_t b0 = __float_as_uint(Vs[(kb * 8 + tig)     * KP + nt * 8 + g]);
                uint32_t b1 = __float_as_uint(Vs[(kb * 8 + tig + 4) * KP + nt * 8 + g]);
                mma_tf32(oa[nt][0], oa[nt][1], oa[nt][2], oa[nt][3],
                         a0, a1, a2, a3, b0, b1);
            }
        }
    }

    // write O
    float inv0 = 1.f / l_i[0], inv1 = 1.f / l_i[1];
    size_t tok0 = tokbase + qb * 64 + wrow + g;
    size_t tok1 = tok0 + 8;
    #pragma unroll
    for (int nt = 0; nt < 8; ++nt) {
        int c = qoff + nt * 8 + 2 * tig;
        float2 p0 = {oa[nt][0] * inv0, oa[nt][1] * inv0};
        float2 p1 = {oa[nt][2] * inv1, oa[nt][3] * inv1};
        *(float2*)(o + tok0 * DIM + c) = p0;
        *(float2*)(o + tok1 * DIM + c) = p1;
    }
}

// ---------------------------------------------------------------
extern "C" void kernel_launch(void* const* d_in, const int* in_sizes, int n_in,
                              void* d_out, int out_size)
{
    const float* x     = (const float*)d_in[0];
    const float* n1w   = (const float*)d_in[1];
    const float* qkvw  = (const float*)d_in[2];
    const float* projw = (const float*)d_in[3];
    const float* projb = (const float*)d_in[4];
    const float* n2w   = (const float*)d_in[5];
    const float* fc1w  = (const float*)d_in[6];
    const float* fc1b  = (const float*)d_in[7];
    const float* fc2w  = (const float*)d_in[8];
    const float* fc2b  = (const float*)d_in[9];
    float* out = (float*)d_out;

    float *h, *qkv, *o, *m1;
    cudaGetSymbolAddress((void**)&h,   g_h);
    cudaGetSymbolAddress((void**)&qkv, g_qkv);
    cudaGetSymbolAddress((void**)&o,   g_o);
    cudaGetSymbolAddress((void**)&m1,  g_m1);

    static bool attr_done = false;
    if (!attr_done) {
        cudaFuncSetAttribute(tf32gemm_kernel<false, false, false>,
                             cudaFuncAttributeMaxDynamicSharedMemorySize, GEMM_SMEM);
        cudaFuncSetAttribute(tf32gemm_kernel<true, false, true>,
                             cudaFuncAttributeMaxDynamicSharedMemorySize, GEMM_SMEM);
        cudaFuncSetAttribute(tf32gemm_kernel<true, true, false>,
                             cudaFuncAttributeMaxDynamicSharedMemorySize, GEMM_SMEM);
        cudaFuncSetAttribute(attn_kernel,
                             cudaFuncAttributeMaxDynamicSharedMemorySize, ATTN_SMEM);
        attr_done = true;
    }

    // 1) h = rmsnorm(x, norm1_w)
    rmsnorm_kernel<<<MTOK, 256>>>(x, n1w, h);
    // 2) qkv = h @ qkv_w
    tf32gemm_kernel<false, false, false>
        <<<dim3(3 * DIM / 128, MTOK / 256), 256, GEMM_SMEM>>>(
        h, qkvw, qkv, nullptr, nullptr, 3 * DIM, DIM);
    // 3) attention -> o
    attn_kernel<<<dim3(SEQ / 64, NHEAD, BATCH), 128, ATTN_SMEM>>>(qkv, o);
    // 4) out = x + o @ proj_w + proj_b
    tf32gemm_kernel<true, false, true>
        <<<dim3(DIM / 128, MTOK / 256), 256, GEMM_SMEM>>>(
        o, projw, out, projb, x, DIM, DIM);
    // 5) h = rmsnorm(out, norm2_w)
    rmsnorm_kernel<<<MTOK, 256>>>(out, n2w, h);
    // 6) m1 = silu(h @ fc1_w + fc1_b)
    tf32gemm_kernel<true, true, false>
        <<<dim3(MLPD / 128, MTOK / 256), 256, GEMM_SMEM>>>(
        h, fc1w, m1, fc1b, nullptr, MLPD, DIM);
    // 7) out = out + m1 @ fc2_w + fc2_b
    tf32gemm_kernel<true, false, true>
        <<<dim3(DIM / 128, MTOK / 256), 256, GEMM_SMEM>>>(
        m1, fc2w, out, fc2b, out, DIM, MLPD);
}

// round 5
// speedup vs baseline: 3.2212x; 1.2002x over previous
#include <cuda_runtime.h>
#include <math.h>
#include <stdint.h>

// Problem constants
#define BATCH 4
#define SEQ   2048
#define DIM   1024
#define NHEAD 16
#define HDIM  64
#define MLPD  4096
#define MTOK  (BATCH*SEQ)   // 8192 tokens

// -------- scratch (device globals; no allocation allowed) --------
__device__ __align__(16) float g_h  [(size_t)MTOK * DIM];
__device__ __align__(16) float g_qkv[(size_t)MTOK * 3 * DIM];
__device__ __align__(16) float g_o  [(size_t)MTOK * DIM];
__device__ __align__(16) float g_m1 [(size_t)MTOK * MLPD];

// ---------------------------------------------------------------
// helpers
// ---------------------------------------------------------------
__device__ __forceinline__ void mma_tf32(
    float& d0, float& d1, float& d2, float& d3,
    uint32_t a0, uint32_t a1, uint32_t a2, uint32_t a3,
    uint32_t b0, uint32_t b1)
{
    asm volatile(
        "mma.sync.aligned.m16n8k8.row.col.f32.tf32.tf32.f32 "
        "{%0,%1,%2,%3}, {%4,%5,%6,%7}, {%8,%9}, {%0,%1,%2,%3};\n"
        : "+f"(d0), "+f"(d1), "+f"(d2), "+f"(d3)
        : "r"(a0), "r"(a1), "r"(a2), "r"(a3), "r"(b0), "r"(b1));
}

__device__ __forceinline__ void cp16(uint32_t smem_dst, const void* gsrc) {
    asm volatile("cp.async.cg.shared.global [%0], [%1], 16;\n"
                 :: "r"(smem_dst), "l"(gsrc));
}
__device__ __forceinline__ void cp_commit() {
    asm volatile("cp.async.commit_group;\n");
}
__device__ __forceinline__ void cp_wait2() {
    asm volatile("cp.async.wait_group 2;\n");
}

// ---------------------------------------------------------------
// RMSNorm
// ---------------------------------------------------------------
__global__ __launch_bounds__(256) void rmsnorm_kernel(
    const float* __restrict__ x, const float* __restrict__ w, float* __restrict__ y)
{
    int row = blockIdx.x;
    const float4* xr = (const float4*)(x + (size_t)row * DIM);
    float4 v = xr[threadIdx.x];
    float ss = v.x*v.x + v.y*v.y + v.z*v.z + v.w*v.w;
    #pragma unroll
    for (int o = 16; o; o >>= 1) ss += __shfl_xor_sync(0xffffffffu, ss, o);
    __shared__ float red[8];
    if ((threadIdx.x & 31) == 0) red[threadIdx.x >> 5] = ss;
    __syncthreads();
    float tot = 0.f;
    #pragma unroll
    for (int i = 0; i < 8; ++i) tot += red[i];
    float inv = rsqrtf(tot * (1.0f / DIM) + 1e-6f);
    float4 wv = ((const float4*)w)[threadIdx.x];
    float4 out;
    out.x = v.x * inv * wv.x;
    out.y = v.y * inv * wv.y;
    out.z = v.z * inv * wv.z;
    out.w = v.w * inv * wv.w;
    ((float4*)(y + (size_t)row * DIM))[threadIdx.x] = out;
}

// ---------------------------------------------------------------
// TF32 GEMM v3: 256x128 tile, BK=16, 8 warps (64x64 each),
// 4-stage cp.async pipeline (3 tiles in flight).
// ---------------------------------------------------------------
#define AP 20
#define BP 136
#define ASZ (256 * AP)
#define BSZ (16 * BP)
#define STAGES 4
#define GEMM_SMEM (STAGES * (ASZ + BSZ) * 4)

template<bool HAS_BIAS, bool DO_SILU, bool HAS_RES>
__global__ __launch_bounds__(256, 1) void tf32gemm_kernel(
    const float* __restrict__ A, const float* __restrict__ Bm,
    float* __restrict__ C, const float* __restrict__ bias,
    const float* __restrict__ res, int N, int K)
{
    extern __shared__ uint32_t sm[];
    uint32_t* As = sm;                       // [STAGES][ASZ]
    uint32_t* Bs = sm + STAGES * ASZ;        // [STAGES][BSZ]

    const int tid  = threadIdx.x;
    const int lane = tid & 31, warp = tid >> 5;
    const int wm = (warp & 3) * 64;
    const int wn = (warp >> 2) * 64;
    const int g  = lane >> 2, tig = lane & 3;
    const int rowBase = blockIdx.y * 256;
    const int colBase = blockIdx.x * 128;

    const uint32_t sbase = (uint32_t)__cvta_generic_to_shared(sm);

    const int ar0 = tid >> 2;
    const int akq = (tid & 3) << 2;
    const int br0 = tid >> 5;
    const int bc  = (tid & 31) << 2;

    auto ldg_async = [&](int k0, int buf) {
        uint32_t abase = sbase + (buf * ASZ) * 4;
        #pragma unroll
        for (int it = 0; it < 4; ++it) {
            int row = ar0 + it * 64;
            cp16(abase + (row * AP + akq) * 4,
                 A + (size_t)(rowBase + row) * K + k0 + akq);
        }
        uint32_t bbase = sbase + (STAGES * ASZ + buf * BSZ) * 4;
        #pragma unroll
        for (int it = 0; it < 2; ++it) {
            int row = br0 + it * 8;
            cp16(bbase + (row * BP + bc) * 4,
                 Bm + (size_t)(k0 + row) * N + colBase + bc);
        }
        cp_commit();
    };

    float acc[4][8][4];
    #pragma unroll
    for (int mt = 0; mt < 4; ++mt)
        #pragma unroll
        for (int nt = 0; nt < 8; ++nt)
            #pragma unroll
            for (int q = 0; q < 4; ++q) acc[mt][nt][q] = 0.f;

    auto compute = [&](int buf) {
        const uint32_t* Ab = As + buf * ASZ;
        const uint32_t* Bb = Bs + buf * BSZ;
        #pragma unroll
        for (int k8 = 0; k8 < 2; ++k8) {
            const int kb = k8 * 8;
            uint32_t af[4][4];
            #pragma unroll
            for (int mt = 0; mt < 4; ++mt) {
                int r = wm + mt * 16 + g;
                af[mt][0] = Ab[ r      * AP + kb + tig];
                af[mt][1] = Ab[(r + 8) * AP + kb + tig];
                af[mt][2] = Ab[ r      * AP + kb + tig + 4];
                af[mt][3] = Ab[(r + 8) * AP + kb + tig + 4];
            }
            uint32_t bf[8][2];
            #pragma unroll
            for (int nt = 0; nt < 8; ++nt) {
                int c = wn + nt * 8 + g;
                bf[nt][0] = Bb[(kb + tig)     * BP + c];
                bf[nt][1] = Bb[(kb + tig + 4) * BP + c];
            }
            #pragma unroll
            for (int mt = 0; mt < 4; ++mt)
                #pragma unroll
                for (int nt = 0; nt < 8; ++nt)
                    mma_tf32(acc[mt][nt][0], acc[mt][nt][1],
                             acc[mt][nt][2], acc[mt][nt][3],
                             af[mt][0], af[mt][1], af[mt][2], af[mt][3],
                             bf[nt][0], bf[nt][1]);
        }
    };

    const int nk = K >> 4;
    // prologue: fill 3 stages
    ldg_async(0, 0);
    ldg_async(16, 1);
    ldg_async(32, 2);

    for (int kt = 0; kt < nk; ++kt) {
        cp_wait2();            // stage kt complete
        __syncthreads();       // all threads done with stage (kt-1)'s buffer
        int pf = kt + STAGES - 1;
        if (pf < nk) ldg_async(pf << 4, pf & (STAGES - 1));
        compute(kt & (STAGES - 1));
    }

    // epilogue
    #pragma unroll
    for (int mt = 0; mt < 4; ++mt) {
        #pragma unroll
        for (int nt = 0; nt < 8; ++nt) {
            int r0 = rowBase + wm + mt * 16 + g;
            int r1 = r0 + 8;
            int c  = colBase + wn + nt * 8 + 2 * tig;
            float v0 = acc[mt][nt][0], v1 = acc[mt][nt][1];
            float v2 = acc[mt][nt][2], v3 = acc[mt][nt][3];
            if (HAS_BIAS) {
                float b0 = bias[c], b1 = bias[c + 1];
                v0 += b0; v1 += b1; v2 += b0; v3 += b1;
            }
            if (DO_SILU) {
                v0 = v0 / (1.f + __expf(-v0));
                v1 = v1 / (1.f + __expf(-v1));
                v2 = v2 / (1.f + __expf(-v2));
                v3 = v3 / (1.f + __expf(-v3));
            }
            if (HAS_RES) {
                v0 += res[(size_t)r0 * N + c];
                v1 += res[(size_t)r0 * N + c + 1];
                v2 += res[(size_t)r1 * N + c];
                v3 += res[(size_t)r1 * N + c + 1];
            }
            float2 p0 = {v0, v1}, p1 = {v2, v3};
            *(float2*)(C + (size_t)r0 * N + c) = p0;
            *(float2*)(C + (size_t)r1 * N + c) = p1;
        }
    }
}

// ---------------------------------------------------------------
// TF32 flash attention v2.
// grid=(SEQ/128, NHEAD, BATCH), 256 threads (8 warps x 16 query rows).
// Fragment-packed smem:
//  Qf/Pf: A-fragment packs, group (kb,tig) -> 64 float4 (one per (w,g)),
//         row pitch 264 words (==8 mod 32 -> LDS.128 conflict-free).
//  Kp/Vp: B-fragment pairs, group (kb,tig) -> 64 float2 (per col),
//         row pitch 136 words (==8 mod 32 -> LDS.64 conflict-free).
// ---------------------------------------------------------------
#define QF_SZ (32 * 264)   // 8448 words
#define KP_SZ (32 * 136)   // 4352 words
#define ATTN_SMEM ((2 * QF_SZ + 2 * KP_SZ) * 4)   // 102400 B

__global__ __launch_bounds__(256) void attn_kernel(
    const float* __restrict__ qkv, float* __restrict__ o)
{
    extern __shared__ float smf[];
    float* Qf = smf;
    float* Pf = Qf + QF_SZ;
    float* Kp = Pf + QF_SZ;
    float* Vp = Kp + KP_SZ;

    const int tid  = threadIdx.x;
    const int lane = tid & 31, warp = tid >> 5;   // warp 0..7
    const int g = lane >> 2, tig = lane & 3;

    const int qb = blockIdx.x, h = blockIdx.y, b = blockIdx.z;
    const size_t tokbase = (size_t)b * SEQ;
    const int qrow0 = qb * 128;
    const int qoff = h * HDIM;
    const int koff = DIM + h * HDIM;
    const int voff = 2 * DIM + h * HDIM;

    // ---- stage Q into fragment-packed layout ----
    {
        int r  = tid >> 1;               // query row 0..127
        int d0 = (tid & 1) * 32;
        int w_ = r >> 4, g_ = r & 7, rb = (r >> 3) & 1;
        int rg4 = (w_ * 8 + g_) * 4 + rb;
        const float* src = qkv + (tokbase + qrow0 + r) * (size_t)(3 * DIM) + qoff + d0;
        #pragma unroll
        for (int u = 0; u < 8; ++u) {
            float4 a = *(const float4*)(src + u * 4);
            float vals[4] = {a.x, a.y, a.z, a.w};
            #pragma unroll
            for (int c = 0; c < 4; ++c) {
                int d = d0 + u * 4 + c;
                int kb = d >> 3, t = d & 7;
                Qf[(kb * 4 + (t & 3)) * 264 + rg4 + (t >> 2) * 2] = vals[c];
            }
        }
    }

    float m_i[2], l_i[2], oa[8][4];
    m_i[0] = m_i[1] = -1e30f;
    l_i[0] = l_i[1] = 0.f;
    #pragma unroll
    for (int nt = 0; nt < 8; ++nt)
        #pragma unroll
        for (int q = 0; q < 4; ++q) oa[nt][q] = 0.f;

    const int wg4 = (warp * 8 + g) * 4;

    for (int t = 0; t < SEQ / 64; ++t) {
        __syncthreads();   // previous-iter readers of Kp/Vp done (covers Q stage at t=0)
        // ---- stage K and V (packed) ----
        {
            int r  = tid >> 2;           // key 0..63
            int d0 = (tid & 3) * 16;
            int kbv = r >> 3, tv = r & 7;
            int vrow = (kbv * 4 + (tv & 3)) * 136 + (tv >> 2);
            const float* ksrc = qkv + (tokbase + t * 64 + r) * (size_t)(3 * DIM) + koff + d0;
            const float* vsrc = qkv + (tokbase + t * 64 + r) * (size_t)(3 * DIM) + voff + d0;
            #pragma unroll
            for (int u = 0; u < 4; ++u) {
                float4 kk = *(const float4*)(ksrc + u * 4);
                float4 vv = *(const float4*)(vsrc + u * 4);
                float kvals[4] = {kk.x, kk.y, kk.z, kk.w};
                float vvals[4] = {vv.x, vv.y, vv.z, vv.w};
                #pragma unroll
                for (int c = 0; c < 4; ++c) {
                    int d = d0 + u * 4 + c;
                    int kbd = d >> 3, td = d & 7;
                    Kp[(kbd * 4 + (td & 3)) * 136 + r * 2 + (td >> 2)] = kvals[c];
                    Vp[vrow + d * 2] = vvals[c];
                }
            }
        }
        __syncthreads();

        // ---- S = Q @ K^T (per warp: 16 rows x 64 keys) ----
        float s[8][4];
        #pragma unroll
        for (int nt = 0; nt < 8; ++nt)
            #pragma unroll
            for (int q = 0; q < 4; ++q) s[nt][q] = 0.f;
        #pragma unroll
        for (int kb = 0; kb < 8; ++kb) {
            float4 aq = *(float4*)&Qf[(kb * 4 + tig) * 264 + wg4];
            uint32_t a0 = __float_as_uint(aq.x), a1 = __float_as_uint(aq.y);
            uint32_t a2 = __float_as_uint(aq.z), a3 = __float_as_uint(aq.w);
            #pragma unroll
            for (int nt = 0; nt < 8; ++nt) {
                float2 b2 = *(float2*)&Kp[(kb * 4 + tig) * 136 + (nt * 8 + g) * 2];
                mma_tf32(s[nt][0], s[nt][1], s[nt][2], s[nt][3],
                         a0, a1, a2, a3,
                         __float_as_uint(b2.x), __float_as_uint(b2.y));
            }
        }

        // ---- online softmax (rows g, g+8 of warp band) ----
        const float scale = 0.125f;
        float mx0 = -1e30f, mx1 = -1e30f;
        #pragma unroll
        for (int nt = 0; nt < 8; ++nt) {
            s[nt][0] *= scale; s[nt][1] *= scale;
            s[nt][2] *= scale; s[nt][3] *= scale;
            mx0 = fmaxf(mx0, fmaxf(s[nt][0], s[nt][1]));
            mx1 = fmaxf(mx1, fmaxf(s[nt][2], s[nt][3]));
        }
        #pragma unroll
        for (int off = 1; off <= 2; off <<= 1) {
            mx0 = fmaxf(mx0, __shfl_xor_sync(0xffffffffu, mx0, off));
            mx1 = fmaxf(mx1, __shfl_xor_sync(0xffffffffu, mx1, off));
        }
        float mn0 = fmaxf(m_i[0], mx0), mn1 = fmaxf(m_i[1], mx1);
        float al0 = __expf(m_i[0] - mn0), al1 = __expf(m_i[1] - mn1);
        float rs0 = 0.f, rs1 = 0.f;
        #pragma unroll
        for (int nt = 0; nt < 8; ++nt) {
            s[nt][0] = __expf(s[nt][0] - mn0);
            s[nt][1] = __expf(s[nt][1] - mn0);
            s[nt][2] = __expf(s[nt][2] - mn1);
            s[nt][3] = __expf(s[nt][3] - mn1);
            rs0 += s[nt][0] + s[nt][1];
            rs1 += s[nt][2] + s[nt][3];
        }
        #pragma unroll
        for (int off = 1; off <= 2; off <<= 1) {
            rs0 += __shfl_xor_sync(0xffffffffu, rs0, off);
            rs1 += __shfl_xor_sync(0xffffffffu, rs1, off);
        }
        l_i[0] = l_i[0] * al0 + rs0;
        l_i[1] = l_i[1] * al1 + rs1;
        m_i[0] = mn0; m_i[1] = mn1;
        #pragma unroll
        for (int nt = 0; nt < 8; ++nt) {
            oa[nt][0] *= al0; oa[nt][1] *= al0;
            oa[nt][2] *= al1; oa[nt][3] *= al1;
        }

        // ---- stage P into fragment-packed layout (warp-private rows) ----
        {
            int tp0 = 2 * tig;           // col offset within 8-group for c even
            int tg0 = tp0 & 3, s0 = tp0 >> 2;
            int tp1 = 2 * tig + 1;
            int tg1 = tp1 & 3, s1 = tp1 >> 2;
            #pragma unroll
            for (int nt = 0; nt < 8; ++nt) {
                float* b0 = &Pf[(nt * 4 + tg0) * 264 + wg4 + s0 * 2];
                b0[0] = s[nt][0];        // row g,   col nt*8+2tig
                b0[1] = s[nt][2];        // row g+8, col nt*8+2tig
                float* b1 = &Pf[(nt * 4 + tg1) * 264 + wg4 + s1 * 2];
                b1[0] = s[nt][1];        // row g,   col nt*8+2tig+1
                b1[1] = s[nt][3];        // row g+8, col nt*8+2tig+1
            }
        }
        __syncwarp();

        // ---- O += P @ V ----
        #pragma unroll
        for (int kb = 0; kb < 8; ++kb) {
            float4 ap = *(float4*)&Pf[(kb * 4 + tig) * 264 + wg4];
            uint32_t a0 = __float_as_uint(ap.x), a1 = __float_as_uint(ap.y);
            uint32_t a2 = __float_as_uint(ap.z), a3 = __float_as_uint(ap.w);
            #pragma unroll
            for (int nt = 0; nt < 8; ++nt) {
                float2 b2 = *(float2*)&Vp[(kb * 4 + tig) * 136 + (nt * 8 + g) * 2];
                mma_tf32(oa[nt][0], oa[nt][1], oa[nt][2], oa[nt][3],
                         a0, a1, a2, a3,
                         __float_as_uint(b2.x), __float_as_uint(b2.y));
            }
        }
        __syncwarp();
    }

    // ---- write O ----
    float inv0 = 1.f / l_i[0], inv1 = 1.f / l_i[1];
    size_t tok0 = tokbase + qrow0 + warp * 16 + g;
    size_t tok1 = tok0 + 8;
    #pragma unroll
    for (int nt = 0; nt < 8; ++nt) {
        int c = qoff + nt * 8 + 2 * tig;
        float2 p0 = {oa[nt][0] * inv0, oa[nt][1] * inv0};
        float2 p1 = {oa[nt][2] * inv1, oa[nt][3] * inv1};
        *(float2*)(o + tok0 * DIM + c) = p0;
        *(float2*)(o + tok1 * DIM + c) = p1;
    }
}

// ---------------------------------------------------------------
extern "C" void kernel_launch(void* const* d_in, const int* in_sizes, int n_in,
                              void* d_out, int out_size)
{
    const float* x     = (const float*)d_in[0];
    const float* n1w   = (const float*)d_in[1];
    const float* qkvw  = (const float*)d_in[2];
    const float* projw = (const float*)d_in[3];
    const float* projb = (const float*)d_in[4];
    const float* n2w   = (const float*)d_in[5];
    const float* fc1w  = (const float*)d_in[6];
    const float* fc1b  = (const float*)d_in[7];
    const float* fc2w  = (const float*)d_in[8];
    const float* fc2b  = (const float*)d_in[9];
    float* out = (float*)d_out;

    float *h, *qkv, *o, *m1;
    cudaGetSymbolAddress((void**)&h,   g_h);
    cudaGetSymbolAddress((void**)&qkv, g_qkv);
    cudaGetSymbolAddress((void**)&o,   g_o);
    cudaGetSymbolAddress((void**)&m1,  g_m1);

    static bool attr_done = false;
    if (!attr_done) {
        cudaFuncSetAttribute(tf32gemm_kernel<false, false, false>,
                             cudaFuncAttributeMaxDynamicSharedMemorySize, GEMM_SMEM);
        cudaFuncSetAttribute(tf32gemm_kernel<true, false, true>,
                             cudaFuncAttributeMaxDynamicSharedMemorySize, GEMM_SMEM);
        cudaFuncSetAttribute(tf32gemm_kernel<true, true, false>,
                             cudaFuncAttributeMaxDynamicSharedMemorySize, GEMM_SMEM);
        cudaFuncSetAttribute(attn_kernel,
                             cudaFuncAttributeMaxDynamicSharedMemorySize, ATTN_SMEM);
        attr_done = true;
    }

    // 1) h = rmsnorm(x, norm1_w)
    rmsnorm_kernel<<<MTOK, 256>>>(x, n1w, h);
    // 2) qkv = h @ qkv_w
    tf32gemm_kernel<false, false, false>
        <<<dim3(3 * DIM / 128, MTOK / 256), 256, GEMM_SMEM>>>(
        h, qkvw, qkv, nullptr, nullptr, 3 * DIM, DIM);
    // 3) attention -> o
    attn_kernel<<<dim3(SEQ / 128, NHEAD, BATCH), 256, ATTN_SMEM>>>(qkv, o);
    // 4) out = x + o @ proj_w + proj_b
    tf32gemm_kernel<true, false, true>
        <<<dim3(DIM / 128, MTOK / 256), 256, GEMM_SMEM>>>(
        o, projw, out, projb, x, DIM, DIM);
    // 5) h = rmsnorm(out, norm2_w)
    rmsnorm_kernel<<<MTOK, 256>>>(out, n2w, h);
    // 6) m1 = silu(h @ fc1_w + fc1_b)
    tf32gemm_kernel<true, true, false>
        <<<dim3(MLPD / 128, MTOK / 256), 256, GEMM_SMEM>>>(
        h, fc1w, m1, fc1b, nullptr, MLPD, DIM);
    // 7) out = out + m1 @ fc2_w + fc2_b
    tf32gemm_kernel<true, false, true>
        <<<dim3(DIM / 128, MTOK / 256), 256, GEMM_SMEM>>>(
        m1, fc2w, out, fc2b, out, DIM, MLPD);
}

// round 7
// speedup vs baseline: 5.9594x; 1.8500x over previous
#include <cuda_runtime.h>
#include <cuda_fp16.h>
#include <math.h>
#include <stdint.h>

// Problem constants
#define BATCH 4
#define SEQ   2048
#define DIM   1024
#define NHEAD 16
#define HDIM  64
#define MLPD  4096
#define MTOK  (BATCH*SEQ)   // 8192 tokens

// -------- scratch (device globals; no allocation allowed) --------
__device__ __align__(16) __half g_h  [(size_t)MTOK * DIM];        // 16 MB
__device__ __align__(16) __half g_qkv[(size_t)MTOK * 3 * DIM];    // 48 MB
__device__ __align__(16) __half g_o  [(size_t)MTOK * DIM];        // 16 MB
__device__ __align__(16) __half g_m1 [(size_t)MTOK * MLPD];       // 64 MB
// pair-interleaved half weights: Wp[k/2][n] = (w[2k][n], w[2k+1][n])
__device__ __align__(16) __half2 g_qkvwP [(size_t)(DIM/2) * 3 * DIM];
__device__ __align__(16) __half2 g_projwP[(size_t)(DIM/2) * DIM];
__device__ __align__(16) __half2 g_fc1wP [(size_t)(DIM/2) * MLPD];
__device__ __align__(16) __half2 g_fc2wP [(size_t)(MLPD/2) * DIM];

// ---------------------------------------------------------------
// helpers
// ---------------------------------------------------------------
__device__ __forceinline__ void mma_f16(
    float& d0, float& d1, float& d2, float& d3,
    uint32_t a0, uint32_t a1, uint32_t a2, uint32_t a3,
    uint32_t b0, uint32_t b1)
{
    asm volatile(
        "mma.sync.aligned.m16n8k16.row.col.f32.f16.f16.f32 "
        "{%0,%1,%2,%3}, {%4,%5,%6,%7}, {%8,%9}, {%0,%1,%2,%3};\n"
        : "+f"(d0), "+f"(d1), "+f"(d2), "+f"(d3)
        : "r"(a0), "r"(a1), "r"(a2), "r"(a3), "r"(b0), "r"(b1));
}
__device__ __forceinline__ void cp16(uint32_t smem_dst, const void* gsrc) {
    asm volatile("cp.async.cg.shared.global [%0], [%1], 16;\n"
                 :: "r"(smem_dst), "l"(gsrc));
}
__device__ __forceinline__ void cp_commit() {
    asm volatile("cp.async.commit_group;\n");
}
__device__ __forceinline__ void cp_wait1() {
    asm volatile("cp.async.wait_group 1;\n");
}

// ---------------------------------------------------------------
// Weight convert: fp32 W[K][N] -> half2 pair-interleaved Wp[k2][n]
// ---------------------------------------------------------------
__global__ __launch_bounds__(256) void convw_kernel(
    const float* __restrict__ in, __half2* __restrict__ out, int N)
{
    int n  = blockIdx.x * 256 + threadIdx.x;
    int k2 = blockIdx.y;
    float a = in[(size_t)(2 * k2) * N + n];
    float b = in[(size_t)(2 * k2 + 1) * N + n];
    out[(size_t)k2 * N + n] = __floats2half2_rn(a, b);
}

// ---------------------------------------------------------------
// RMSNorm: fp32 in -> half out
// ---------------------------------------------------------------
__global__ __launch_bounds__(256) void rmsnorm_kernel(
    const float* __restrict__ x, const float* __restrict__ w, __half* __restrict__ y)
{
    int row = blockIdx.x;
    const float4* xr = (const float4*)(x + (size_t)row * DIM);
    float4 v = xr[threadIdx.x];
    float ss = v.x*v.x + v.y*v.y + v.z*v.z + v.w*v.w;
    #pragma unroll
    for (int o = 16; o; o >>= 1) ss += __shfl_xor_sync(0xffffffffu, ss, o);
    __shared__ float red[8];
    if ((threadIdx.x & 31) == 0) red[threadIdx.x >> 5] = ss;
    __syncthreads();
    float tot = 0.f;
    #pragma unroll
    for (int i = 0; i < 8; ++i) tot += red[i];
    float inv = rsqrtf(tot * (1.0f / DIM) + 1e-6f);
    float4 wv = ((const float4*)w)[threadIdx.x];
    __half2 h0 = __floats2half2_rn(v.x * inv * wv.x, v.y * inv * wv.y);
    __half2 h1 = __floats2half2_rn(v.z * inv * wv.z, v.w * inv * wv.w);
    __half2* yo = (__half2*)(y + (size_t)row * DIM) + threadIdx.x * 2;
    yo[0] = h0; yo[1] = h1;
}

// ---------------------------------------------------------------
// FP16 mma GEMM: C[M,N] = A[M,K] @ W (+bias)(+silu)(+res)
// A half row-major; W pair-interleaved half2 [K/2][N].
// Block 256x128, BK=32, 8 warps (4x2), warp tile 64x64, 3-stage cp.async.
// ---------------------------------------------------------------
#define AP2 20            // A pitch in half2 (16 + 4 pad)
#define BP2 136           // B pitch in half2 (128 + 8 pad)
#define ASTG_B (256 * AP2 * 4)   // 20480 B per stage
#define BSTG_B (16 * BP2 * 4)    // 8704 B per stage
#define GSTAGES 3
#define GEMM_SMEM (GSTAGES * (ASTG_B + BSTG_B))   // 87552 B

template<bool OUT_HALF, bool HAS_BIAS, bool DO_SILU, bool HAS_RES>
__global__ __launch_bounds__(256, 1) void gemm16_kernel(
    const __half* __restrict__ A, const __half2* __restrict__ Bp,
    void* __restrict__ Cv, const float* __restrict__ bias,
    const float* __restrict__ res, int N, int K)
{
    extern __shared__ __align__(16) char dsm[];

    const int tid  = threadIdx.x;
    const int lane = tid & 31, warp = tid >> 5;
    const int wm = (warp & 3) * 64;
    const int wn = (warp >> 2) * 64;
    const int g  = lane >> 2, tig = lane & 3;
    const int rowBase = blockIdx.y * 256;
    const int colBase = blockIdx.x * 128;
    const uint32_t sbase = (uint32_t)__cvta_generic_to_shared(dsm);

    auto ldg = [&](int t, int buf) {
        int k0 = t << 5;
        uint32_t ab = sbase + buf * ASTG_B;
        #pragma unroll
        for (int it = 0; it < 4; ++it) {
            int cid = tid + it * 256;          // 1024 chunks (256 rows x 4)
            int row = cid >> 2, ch = cid & 3;
            cp16(ab + (row * AP2 + ch * 4) * 4,
                 A + (size_t)(rowBase + row) * K + k0 + ch * 8);
        }
        uint32_t bb = sbase + GSTAGES * ASTG_B + buf * BSTG_B;
        #pragma unroll
        for (int it = 0; it < 2; ++it) {
            int cid = tid + it * 256;          // 512 chunks (16 k2-rows x 32)
            int k2 = cid >> 5, nc = (cid & 31) * 4;
            cp16(bb + (k2 * BP2 + nc) * 4,
                 Bp + (size_t)((k0 >> 1) + k2) * N + colBase + nc);
        }
        cp_commit();
    };

    float acc[4][8][4];
    #pragma unroll
    for (int mt = 0; mt < 4; ++mt)
        #pragma unroll
        for (int nt = 0; nt < 8; ++nt)
            #pragma unroll
            for (int q = 0; q < 4; ++q) acc[mt][nt][q] = 0.f;

    auto compute = [&](int buf) {
        const uint32_t* Ab = (const uint32_t*)(dsm + buf * ASTG_B);
        const uint32_t* Bb = (const uint32_t*)(dsm + GSTAGES * ASTG_B + buf * BSTG_B);
        #pragma unroll
        for (int s = 0; s < 2; ++s) {
            const int kb2 = s * 8;
            uint32_t af[4][4];
            #pragma unroll
            for (int mt = 0; mt < 4; ++mt) {
                int r = wm + mt * 16 + g;
                af[mt][0] = Ab[ r      * AP2 + kb2 + tig];
                af[mt][1] = Ab[(r + 8) * AP2 + kb2 + tig];
                af[mt][2] = Ab[ r      * AP2 + kb2 + tig + 4];
                af[mt][3] = Ab[(r + 8) * AP2 + kb2 + tig + 4];
            }
            uint32_t bf[8][2];
            #pragma unroll
            for (int nt = 0; nt < 8; ++nt) {
                int c = wn + nt * 8 + g;
                bf[nt][0] = Bb[(kb2 + tig)     * BP2 + c];
                bf[nt][1] = Bb[(kb2 + tig + 4) * BP2 + c];
            }
            #pragma unroll
            for (int mt = 0; mt < 4; ++mt)
                #pragma unroll
                for (int nt = 0; nt < 8; ++nt)
                    mma_f16(acc[mt][nt][0], acc[mt][nt][1],
                            acc[mt][nt][2], acc[mt][nt][3],
                            af[mt][0], af[mt][1], af[mt][2], af[mt][3],
                            bf[nt][0], bf[nt][1]);
        }
    };

    const int nk = K >> 5;
    ldg(0, 0);
    ldg(1, 1);
    for (int t = 0; t < nk; ++t) {
        cp_wait1();
        __syncthreads();
        if (t + 2 < nk) ldg(t + 2, (t + 2) % GSTAGES);
        compute(t % GSTAGES);
    }

    // epilogue
    #pragma unroll
    for (int mt = 0; mt < 4; ++mt) {
        #pragma unroll
        for (int nt = 0; nt < 8; ++nt) {
            int r0 = rowBase + wm + mt * 16 + g;
            int r1 = r0 + 8;
            int c  = colBase + wn + nt * 8 + 2 * tig;
            float v0 = acc[mt][nt][0], v1 = acc[mt][nt][1];
            float v2 = acc[mt][nt][2], v3 = acc[mt][nt][3];
            if (HAS_BIAS) {
                float2 bv = *(const float2*)&bias[c];
                v0 += bv.x; v1 += bv.y; v2 += bv.x; v3 += bv.y;
            }
            if (DO_SILU) {
                v0 = v0 / (1.f + __expf(-v0));
                v1 = v1 / (1.f + __expf(-v1));
                v2 = v2 / (1.f + __expf(-v2));
                v3 = v3 / (1.f + __expf(-v3));
            }
            if (HAS_RES) {
                float2 rv0 = *(const float2*)&res[(size_t)r0 * N + c];
                float2 rv1 = *(const float2*)&res[(size_t)r1 * N + c];
                v0 += rv0.x; v1 += rv0.y; v2 += rv1.x; v3 += rv1.y;
            }
            if (OUT_HALF) {
                __half* C = (__half*)Cv;
                *(__half2*)(C + (size_t)r0 * N + c) = __floats2half2_rn(v0, v1);
                *(__half2*)(C + (size_t)r1 * N + c) = __floats2half2_rn(v2, v3);
            } else {
                float* C = (float*)Cv;
                float2 p0 = {v0, v1}, p1 = {v2, v3};
                *(float2*)(C + (size_t)r0 * N + c) = p0;
                *(float2*)(C + (size_t)r1 * N + c) = p1;
            }
        }
    }
}

// ---------------------------------------------------------------
// FP16 flash attention. grid=(SEQ/128, NHEAD, BATCH), 256 threads.
// Fragment-packed half2 smem:
//  Qf/Pf: A-frag packs, rows (kb*4+tg) of 264 half2, per-(w,g) 4 half2.
//  Kp/Vp: B-frag pairs, rows m (=h2 idx of k-dim) of 72 half2.
// ---------------------------------------------------------------
#define QF2_SZ (16 * 264)   // half2 count
#define KP2_SZ (32 * 72)
#define ATTN_SMEM ((2 * QF2_SZ + 2 * KP2_SZ) * 4)   // 52224 B

__global__ __launch_bounds__(256) void attn_kernel(
    const __half* __restrict__ qkv, __half* __restrict__ o)
{
    extern __shared__ __align__(16) uint32_t sm2[];
    uint32_t* Qf = sm2;               // [16][264]
    uint32_t* Pf = Qf + QF2_SZ;
    uint32_t* Kp = Pf + QF2_SZ;       // [32][72]
    uint32_t* Vp = Kp + KP2_SZ;

    const int tid  = threadIdx.x;
    const int lane = tid & 31, warp = tid >> 5;
    const int g = lane >> 2, tig = lane & 3;

    const int qb = blockIdx.x, h = blockIdx.y, b = blockIdx.z;
    const size_t tokbase = (size_t)b * SEQ;
    const int qrow0 = qb * 128;
    const int qoff = h * HDIM;
    const int koff = DIM + h * HDIM;
    const int voff = 2 * DIM + h * HDIM;

    // ---- stage Q (A-frag pack) ----
    {
        int r  = tid >> 1;               // query row 0..127
        int d0 = (tid & 1) * 32;         // 32 halfs
        int w_ = r >> 4, g_ = r & 7, rb = (r >> 3) & 1;
        int posb = (w_ * 8 + g_) * 4 + rb;
        const __half* src = qkv + (tokbase + qrow0 + r) * (size_t)(3 * DIM) + qoff + d0;
        #pragma unroll
        for (int u = 0; u < 4; ++u) {
            uint4 ch = *(const uint4*)(src + u * 8);
            uint32_t w4[4] = {ch.x, ch.y, ch.z, ch.w};
            #pragma unroll
            for (int j = 0; j < 4; ++j) {
                int m = ((d0 + u * 8) >> 1) + j;
                int kb = m >> 3, mm = m & 7;
                int tg = mm & 3, slot = mm >> 2;
                Qf[(kb * 4 + tg) * 264 + posb + slot * 2] = w4[j];
            }
        }
    }

    float m_i[2], l_i[2], oa[8][4];
    m_i[0] = m_i[1] = -1e30f;
    l_i[0] = l_i[1] = 0.f;
    #pragma unroll
    for (int nt = 0; nt < 8; ++nt)
        #pragma unroll
        for (int q = 0; q < 4; ++q) oa[nt][q] = 0.f;

    const int wg4 = (warp * 8 + g) * 4;

    for (int t = 0; t < SEQ / 64; ++t) {
        __syncthreads();
        // ---- stage K (B-frag rows m = d/2) ----
        {
            int r  = tid >> 2;           // key 0..63
            int d0 = (tid & 3) * 16;     // 16 halfs
            const __half* ksrc = qkv + (tokbase + t * 64 + r) * (size_t)(3 * DIM) + koff + d0;
            #pragma unroll
            for (int u = 0; u < 2; ++u) {
                uint4 ch = *(const uint4*)(ksrc + u * 8);
                uint32_t w4[4] = {ch.x, ch.y, ch.z, ch.w};
                #pragma unroll
                for (int j = 0; j < 4; ++j) {
                    int m = ((d0 + u * 8) >> 1) + j;
                    Kp[m * 72 + r] = w4[j];
                }
            }
        }
        // ---- stage V (B-frag rows kp = key/2, needs key-pair interleave) ----
        {
            int kp = tid & 31;           // key pair
            int d0 = (tid >> 5) * 8;     // 8 halfs
            const __half* v0p = qkv + (tokbase + t * 64 + 2 * kp)     * (size_t)(3 * DIM) + voff + d0;
            const __half* v1p = qkv + (tokbase + t * 64 + 2 * kp + 1) * (size_t)(3 * DIM) + voff + d0;
            uint4 c0 = *(const uint4*)v0p;
            uint4 c1 = *(const uint4*)v1p;
            const __half2* h0 = (const __half2*)&c0;
            const __half2* h1 = (const __half2*)&c1;
            __half2* vrow = (__half2*)&Vp[kp * 72 + d0];
            #pragma unroll
            for (int j = 0; j < 4; ++j) {
                vrow[2 * j]     = __halves2half2(__low2half(h0[j]),  __low2half(h1[j]));
                vrow[2 * j + 1] = __halves2half2(__high2half(h0[j]), __high2half(h1[j]));
            }
        }
        __syncthreads();

        // ---- S = Q @ K^T ----
        float s[8][4];
        #pragma unroll
        for (int nt = 0; nt < 8; ++nt)
            #pragma unroll
            for (int q = 0; q < 4; ++q) s[nt][q] = 0.f;
        #pragma unroll
        for (int kb = 0; kb < 4; ++kb) {
            uint4 aq = *(uint4*)&Qf[(kb * 4 + tig) * 264 + wg4];
            #pragma unroll
            for (int nt = 0; nt < 8; ++nt) {
                uint32_t b0 = Kp[(kb * 8 + tig)     * 72 + nt * 8 + g];
                uint32_t b1 = Kp[(kb * 8 + tig + 4) * 72 + nt * 8 + g];
                mma_f16(s[nt][0], s[nt][1], s[nt][2], s[nt][3],
                        aq.x, aq.y, aq.z, aq.w, b0, b1);
            }
        }

        // ---- online softmax ----
        const float scale = 0.125f;
        float mx0 = -1e30f, mx1 = -1e30f;
        #pragma unroll
        for (int nt = 0; nt < 8; ++nt) {
            s[nt][0] *= scale; s[nt][1] *= scale;
            s[nt][2] *= scale; s[nt][3] *= scale;
            mx0 = fmaxf(mx0, fmaxf(s[nt][0], s[nt][1]));
            mx1 = fmaxf(mx1, fmaxf(s[nt][2], s[nt][3]));
        }
        #pragma unroll
        for (int off = 1; off <= 2; off <<= 1) {
            mx0 = fmaxf(mx0, __shfl_xor_sync(0xffffffffu, mx0, off));
            mx1 = fmaxf(mx1, __shfl_xor_sync(0xffffffffu, mx1, off));
        }
        float mn0 = fmaxf(m_i[0], mx0), mn1 = fmaxf(m_i[1], mx1);
        float al0 = __expf(m_i[0] - mn0), al1 = __expf(m_i[1] - mn1);
        float rs0 = 0.f, rs1 = 0.f;
        #pragma unroll
        for (int nt = 0; nt < 8; ++nt) {
            s[nt][0] = __expf(s[nt][0] - mn0);
            s[nt][1] = __expf(s[nt][1] - mn0);
            s[nt][2] = __expf(s[nt][2] - mn1);
            s[nt][3] = __expf(s[nt][3] - mn1);
            rs0 += s[nt][0] + s[nt][1];
            rs1 += s[nt][2] + s[nt][3];
        }
        #pragma unroll
        for (int off = 1; off <= 2; off <<= 1) {
            rs0 += __shfl_xor_sync(0xffffffffu, rs0, off);
            rs1 += __shfl_xor_sync(0xffffffffu, rs1, off);
        }
        l_i[0] = l_i[0] * al0 + rs0;
        l_i[1] = l_i[1] * al1 + rs1;
        m_i[0] = mn0; m_i[1] = mn1;
        #pragma unroll
        for (int nt = 0; nt < 8; ++nt) {
            oa[nt][0] *= al0; oa[nt][1] *= al0;
            oa[nt][2] *= al1; oa[nt][3] *= al1;
        }

        // ---- stage P (A-frag pack, half) ----
        #pragma unroll
        for (int nt = 0; nt < 8; ++nt) {
            int row = (nt >> 1) * 4 + tig;
            int off = wg4 + (nt & 1) * 2;
            __half2* p = (__half2*)&Pf[row * 264 + off];
            p[0] = __floats2half2_rn(s[nt][0], s[nt][1]);   // row g
            p[1] = __floats2half2_rn(s[nt][2], s[nt][3]);   // row g+8
        }
        __syncwarp();

        // ---- O += P @ V ----
        #pragma unroll
        for (int kb = 0; kb < 4; ++kb) {
            uint4 ap = *(uint4*)&Pf[(kb * 4 + tig) * 264 + wg4];
            #pragma unroll
            for (int nt = 0; nt < 8; ++nt) {
                uint32_t b0 = Vp[(kb * 8 + tig)     * 72 + nt * 8 + g];
                uint32_t b1 = Vp[(kb * 8 + tig + 4) * 72 + nt * 8 + g];
                mma_f16(oa[nt][0], oa[nt][1], oa[nt][2], oa[nt][3],
                        ap.x, ap.y, ap.z, ap.w, b0, b1);
            }
        }
        __syncwarp();
    }

    // ---- write O (half) ----
    float inv0 = 1.f / l_i[0], inv1 = 1.f / l_i[1];
    size_t tok0 = tokbase + qrow0 + warp * 16 + g;
    size_t tok1 = tok0 + 8;
    #pragma unroll
    for (int nt = 0; nt < 8; ++nt) {
        int c = qoff + nt * 8 + 2 * tig;
        *(__half2*)(o + tok0 * DIM + c) = __floats2half2_rn(oa[nt][0] * inv0, oa[nt][1] * inv0);
        *(__half2*)(o + tok1 * DIM + c) = __floats2half2_rn(oa[nt][2] * inv1, oa[nt][3] * inv1);
    }
}

// ---------------------------------------------------------------
extern "C" void kernel_launch(void* const* d_in, const int* in_sizes, int n_in,
                              void* d_out, int out_size)
{
    const float* x     = (const float*)d_in[0];
    const float* n1w   = (const float*)d_in[1];
    const float* qkvw  = (const float*)d_in[2];
    const float* projw = (const float*)d_in[3];
    const float* projb = (const float*)d_in[4];
    const float* n2w   = (const float*)d_in[5];
    const float* fc1w  = (const float*)d_in[6];
    const float* fc1b  = (const float*)d_in[7];
    const float* fc2w  = (const float*)d_in[8];
    const float* fc2b  = (const float*)d_in[9];
    float* out = (float*)d_out;

    __half *h, *qkv, *o, *m1;
    __half2 *qkvwP, *projwP, *fc1wP, *fc2wP;
    cudaGetSymbolAddress((void**)&h,      g_h);
    cudaGetSymbolAddress((void**)&qkv,    g_qkv);
    cudaGetSymbolAddress((void**)&o,      g_o);
    cudaGetSymbolAddress((void**)&m1,     g_m1);
    cudaGetSymbolAddress((void**)&qkvwP,  g_qkvwP);
    cudaGetSymbolAddress((void**)&projwP, g_projwP);
    cudaGetSymbolAddress((void**)&fc1wP,  g_fc1wP);
    cudaGetSymbolAddress((void**)&fc2wP,  g_fc2wP);

    static bool attr_done = false;
    if (!attr_done) {
        cudaFuncSetAttribute(gemm16_kernel<true, false, false, false>,
                             cudaFuncAttributeMaxDynamicSharedMemorySize, GEMM_SMEM);
        cudaFuncSetAttribute(gemm16_kernel<false, true, false, true>,
                             cudaFuncAttributeMaxDynamicSharedMemorySize, GEMM_SMEM);
        cudaFuncSetAttribute(gemm16_kernel<true, true, true, false>,
                             cudaFuncAttributeMaxDynamicSharedMemorySize, GEMM_SMEM);
        cudaFuncSetAttribute(attn_kernel,
                             cudaFuncAttributeMaxDynamicSharedMemorySize, ATTN_SMEM);
        attr_done = true;
    }

    // 0) convert weights to pair-interleaved half
    convw_kernel<<<dim3(3 * DIM / 256, DIM / 2), 256>>>(qkvw, qkvwP, 3 * DIM);
    convw_kernel<<<dim3(DIM / 256, DIM / 2),     256>>>(projw, projwP, DIM);
    convw_kernel<<<dim3(MLPD / 256, DIM / 2),    256>>>(fc1w, fc1wP, MLPD);
    convw_kernel<<<dim3(DIM / 256, MLPD / 2),    256>>>(fc2w, fc2wP, DIM);

    // 1) h = rmsnorm(x, norm1_w)  [half]
    rmsnorm_kernel<<<MTOK, 256>>>(x, n1w, h);
    // 2) qkv = h @ qkv_w  [half]
    gemm16_kernel<true, false, false, false>
        <<<dim3(3 * DIM / 128, MTOK / 256), 256, GEMM_SMEM>>>(
        h, qkvwP, qkv, nullptr, nullptr, 3 * DIM, DIM);
    // 3) attention -> o  [half]
    attn_kernel<<<dim3(SEQ / 128, NHEAD, BATCH), 256, ATTN_SMEM>>>(qkv, o);
    // 4) out = x + o @ proj_w + proj_b  [fp32]
    gemm16_kernel<false, true, false, true>
        <<<dim3(DIM / 128, MTOK / 256), 256, GEMM_SMEM>>>(
        o, projwP, out, projb, x, DIM, DIM);
    // 5) h = rmsnorm(out, norm2_w)  [half]
    rmsnorm_kernel<<<MTOK, 256>>>(out, n2w, h);
    // 6) m1 = silu(h @ fc1_w + fc1_b)  [half]
    gemm16_kernel<true, true, true, false>
        <<<dim3(MLPD / 128, MTOK / 256), 256, GEMM_SMEM>>>(
        h, fc1wP, m1, fc1b, nullptr, MLPD, DIM);
    // 7) out = out + m1 @ fc2_w + fc2_b  [fp32]
    gemm16_kernel<false, true, false, true>
        <<<dim3(DIM / 128, MTOK / 256), 256, GEMM_SMEM>>>(
        m1, fc2wP, out, fc2b, out, DIM, MLPD);
}